// round 12
// baseline (speedup 1.0000x reference)
#include <cuda_runtime.h>
#include <cuda_fp16.h>
#include <cstdint>

#define BB 4
#define HH 8
#define NN 2048
#define BHN (BB*HH)
#define MROWS (BB*NN)

// ---------------- scratch (static device, no allocs) ----------------
__device__ __half g_q16[BHN * NN * 32];   // [bh][n][qhi16|qlo16], 0.25*log2e folded
__device__ __half g_k16[BHN * NN * 32];   // [bh][n][khi16|klo16]
__device__ __half g_vh16[BHN * 16 * NN];  // [bh][e][n]  V^T (fp16-rn)
__device__ __half g_Wh[2 * 128 * 128];    // W hi: [q|k][c][k]
__device__ __half g_Wl[2 * 128 * 128];    // W lo residual

// ---------------- helpers ----------------
__device__ __forceinline__ float ex2f_fast(float x) {
    float y; asm("ex2.approx.ftz.f32 %0, %1;" : "=f"(y) : "f"(x)); return y;
}
__device__ __forceinline__ uint32_t ex2_h2(uint32_t x) {
    uint32_t y; asm("ex2.approx.f16x2 %0, %1;" : "=r"(y) : "r"(x)); return y;
}
__device__ __forceinline__ float qmax(float v) {
    v = fmaxf(v, __shfl_xor_sync(0xFFFFFFFFu, v, 1));
    v = fmaxf(v, __shfl_xor_sync(0xFFFFFFFFu, v, 2));
    return v;
}
__device__ __forceinline__ float qsum(float v) {
    v += __shfl_xor_sync(0xFFFFFFFFu, v, 1);
    v += __shfl_xor_sync(0xFFFFFFFFu, v, 2);
    return v;
}
__device__ __forceinline__ void mma_f16(float* d, const uint32_t* a,
                                        uint32_t b0, uint32_t b1) {
    asm volatile(
        "mma.sync.aligned.m16n8k16.row.col.f32.f16.f16.f32 "
        "{%0,%1,%2,%3}, {%4,%5,%6,%7}, {%8,%9}, {%0,%1,%2,%3};"
        : "+f"(d[0]), "+f"(d[1]), "+f"(d[2]), "+f"(d[3])
        : "r"(a[0]), "r"(a[1]), "r"(a[2]), "r"(a[3]), "r"(b0), "r"(b1));
}
// packs: low half <- lo, high half <- hi
__device__ __forceinline__ uint32_t cvt_h2(float lo, float hi) {
    uint32_t r;
    asm("cvt.rn.f16x2.f32 %0, %1, %2;" : "=r"(r) : "f"(hi), "f"(lo));
    return r;
}
__device__ __forceinline__ float2 h2_to_f2(uint32_t u) {
    return __half22float2(*reinterpret_cast<__half2*>(&u));
}
__device__ __forceinline__ void redg_f32(float* p, float v) {
    asm volatile("red.global.add.f32 [%0], %1;" :: "l"(p), "f"(v) : "memory");
}

// ---------------- kernel 1: V proj+transpose, W hi/lo prep, out init ----------------
// blocks [0,512): projvt; [512,768): Wq/Wk split; [768,896): out <- bias.
__global__ void __launch_bounds__(128) prep_kernel(
    const float* __restrict__ value, const float* __restrict__ Wv,
    const float* __restrict__ bv,
    const float* __restrict__ Wq, const float* __restrict__ Wk,
    const float* __restrict__ bo, float* __restrict__ out)
{
    if (blockIdx.x >= 768) {
        const int i = ((blockIdx.x - 768) * 128 + threadIdx.x) * 8;  // 8-aligned
        const int c = i & 15;                                        // 0 or 8
        const float4 b0 = *(const float4*)(bo + c);
        const float4 b1 = *(const float4*)(bo + c + 4);
        *(float4*)(out + i)     = b0;
        *(float4*)(out + i + 4) = b1;
        return;
    }
    if (blockIdx.x >= 512) {
        const int idx = (blockIdx.x - 512) * 128 + threadIdx.x;  // 0..32767
        const int m = idx >> 14, rest = idx & 16383;
        const float x = (m ? Wk : Wq)[rest];
        const __half hi = __float2half_rn(x);
        g_Wh[idx] = hi;
        g_Wl[idx] = __float2half_rn(x - __half2float(hi));
        return;
    }
    __shared__ float Wsm[16][17];
    __shared__ float bsm[16];
    __shared__ __half thi[16][128];
    const int bh = blockIdx.x >> 4, nt = blockIdx.x & 15;
    const int b = bh >> 3, h = bh & 7;
    const int t = threadIdx.x;
    if (t < 16) bsm[t] = bv[h * 16 + t];
    for (int i = t; i < 256; i += 128)
        Wsm[i >> 4][i & 15] = Wv[(h * 16 + (i >> 4)) * 16 + (i & 15)];
    __syncthreads();
    const int n = nt * 128 + t;
    const float4* a = (const float4*)(value + ((size_t)(b * NN + n) << 4));
    const float4 a0 = a[0], a1 = a[1], a2 = a[2], a3 = a[3];
    const float av[16] = {a0.x,a0.y,a0.z,a0.w, a1.x,a1.y,a1.z,a1.w,
                          a2.x,a2.y,a2.z,a2.w, a3.x,a3.y,a3.z,a3.w};
    #pragma unroll
    for (int e = 0; e < 16; e++) {
        float acc = bsm[e];
        #pragma unroll
        for (int k = 0; k < 16; k++) acc = fmaf(av[k], Wsm[e][k], acc);
        thi[e][t] = __float2half_rn(acc);
    }
    __syncthreads();
    for (int i = t; i < 2048; i += 128) {
        const int e = i >> 7, j = i & 127;
        g_vh16[((size_t)bh * 16 + e) * NN + nt * 128 + j] = thi[e][j];
    }
}

// ---------------- Q/K projection on tensor cores ----------------
__global__ void __launch_bounds__(256) projqk_mma_kernel(
    const float* __restrict__ Aq, const float* __restrict__ Ak,
    const float* __restrict__ bq, const float* __restrict__ bk, float alpha_q)
{
    const bool is_k = (blockIdx.y != 0);
    const float* A    = is_k ? Ak : Aq;
    const float* bias = is_k ? bk : bq;
    const __half* Wh  = g_Wh + (is_k ? 16384 : 0);
    const __half* Wl  = g_Wl + (is_k ? 16384 : 0);
    __half* outp      = is_k ? g_k16 : g_q16;
    const float alpha = is_k ? 1.0f : alpha_q;

    const int tid = threadIdx.x, lane = tid & 31, wid = tid >> 5;
    const int rg = wid >> 1, cg = wid & 1;
    const int lq = lane >> 2, lc = lane & 3;
    const int r0 = blockIdx.x * 64 + rg * 16;
    const int c0 = cg * 64;

    uint32_t ah[8][4], al[8][4];
    {
        const float* Ar0 = A + (size_t)(r0 + lq) * 128;
        const float* Ar1 = Ar0 + 8 * 128;
        #pragma unroll
        for (int ks = 0; ks < 8; ks++) {
            const int k0 = ks * 16 + lc * 2;
            float2 f0 = *(const float2*)(Ar0 + k0);
            float2 f1 = *(const float2*)(Ar1 + k0);
            float2 f2 = *(const float2*)(Ar0 + k0 + 8);
            float2 f3 = *(const float2*)(Ar1 + k0 + 8);
            ah[ks][0] = cvt_h2(f0.x, f0.y);
            ah[ks][1] = cvt_h2(f1.x, f1.y);
            ah[ks][2] = cvt_h2(f2.x, f2.y);
            ah[ks][3] = cvt_h2(f3.x, f3.y);
            float2 h0 = h2_to_f2(ah[ks][0]), h1 = h2_to_f2(ah[ks][1]);
            float2 h2 = h2_to_f2(ah[ks][2]), h3 = h2_to_f2(ah[ks][3]);
            al[ks][0] = cvt_h2(f0.x - h0.x, f0.y - h0.y);
            al[ks][1] = cvt_h2(f1.x - h1.x, f1.y - h1.y);
            al[ks][2] = cvt_h2(f2.x - h2.x, f2.y - h2.y);
            al[ks][3] = cvt_h2(f3.x - h3.x, f3.y - h3.y);
        }
    }

    float D[8][4];
    #pragma unroll
    for (int nb = 0; nb < 8; nb++)
        #pragma unroll
        for (int i = 0; i < 4; i++) D[nb][i] = 0.f;

    #pragma unroll
    for (int nb = 0; nb < 8; nb++) {
        const int c = c0 + nb * 8 + lq;
        const __half* whp = Wh + (size_t)c * 128;
        const __half* wlp = Wl + (size_t)c * 128;
        #pragma unroll
        for (int ks = 0; ks < 8; ks++) {
            const int k0 = ks * 16 + lc * 2;
            const uint32_t bh0 = *(const uint32_t*)(whp + k0);
            const uint32_t bh1 = *(const uint32_t*)(whp + k0 + 8);
            const uint32_t bl0 = *(const uint32_t*)(wlp + k0);
            const uint32_t bl1 = *(const uint32_t*)(wlp + k0 + 8);
            mma_f16(D[nb], ah[ks], bh0, bh1);
            mma_f16(D[nb], al[ks], bh0, bh1);
            mma_f16(D[nb], ah[ks], bl0, bl1);
        }
    }

    #pragma unroll
    for (int nb = 0; nb < 8; nb++) {
        const int ce = c0 + nb * 8 + lc * 2;
        const float2 bb = *(const float2*)(bias + ce);
        const int h = ce >> 4, d = ce & 15;
        #pragma unroll
        for (int rr = 0; rr < 2; rr++) {
            const int row = r0 + lq + rr * 8;
            const int b = row >> 11, n = row & 2047;
            __half* base = outp + ((size_t)((b * 8 + h) * 2048 + n)) * 32;
            const float x0 = (D[nb][2*rr + 0] + bb.x) * alpha;
            const float x1 = (D[nb][2*rr + 1] + bb.y) * alpha;
            const uint32_t hi2 = cvt_h2(x0, x1);
            const float2 hf = h2_to_f2(hi2);
            const uint32_t lo2 = cvt_h2(x0 - hf.x, x1 - hf.y);
            *(uint32_t*)(base + d)      = hi2;
            *(uint32_t*)(base + 16 + d) = lo2;
        }
    }
}

// ---------------- fp16 mma.sync flash attention + fused out projection ----------------
// 1024 CTAs = 32 bh x 32 q-tiles of 64 rows; 4 warps; warp owns 16 q-rows; 4 CTAs/SM.
// Softmax exp via ex2.approx.f16x2 (one MUFU per 2 scores; output is the PV fragment).
// Epilogue: o @ Wo_h^T computed in registers, red.global.add.f32 into out.
__global__ void __launch_bounds__(128, 4) attn_mma_kernel(
    const float* __restrict__ Wo, float* __restrict__ out)
{
    __shared__ __align__(16) __half Ksm[128 * 40];   // [key][hi16|lo16|pad8]
    __shared__ __align__(16) __half Vh[16 * 136];    // [e][key]

    const int tid = threadIdx.x, lane = tid & 31, wid = tid >> 5;
    const int bh = blockIdx.x >> 5, qt = blockIdx.x & 31;
    const int qrow0 = qt * 64 + wid * 16;
    const int lq = lane >> 2;
    const int lc = lane & 3;

    uint32_t qh[4], ql[4];
    {
        const __half* p0 = g_q16 + ((size_t)(bh * NN + qrow0 + lq)) * 32 + lc * 2;
        qh[0] = *(const uint32_t*)(p0);
        qh[1] = *(const uint32_t*)(p0 + 256);
        qh[2] = *(const uint32_t*)(p0 + 8);
        qh[3] = *(const uint32_t*)(p0 + 264);
        ql[0] = *(const uint32_t*)(p0 + 16);
        ql[1] = *(const uint32_t*)(p0 + 272);
        ql[2] = *(const uint32_t*)(p0 + 24);
        ql[3] = *(const uint32_t*)(p0 + 280);
    }

    float mr[2] = {-1e30f, -1e30f}, lrow[2] = {0.f, 0.f};
    float o[2][4];
    #pragma unroll
    for (int nb = 0; nb < 2; nb++)
        #pragma unroll
        for (int i = 0; i < 4; i++) o[nb][i] = 0.f;

    const uint4* kg = (const uint4*)(g_k16 + ((size_t)bh * NN) * 32);
    const __half* vhg = g_vh16 + (size_t)bh * 16 * NN;

    for (int t0 = 0; t0 < NN; t0 += 128) {
        __syncthreads();
        #pragma unroll
        for (int g = 0; g < 4; g++) {
            const int j = tid + 128 * g;
            const int key = j >> 2, seg = j & 3;
            *(uint4*)(Ksm + key * 40 + seg * 8) = kg[(size_t)t0 * 4 + j];
        }
        #pragma unroll
        for (int g = 0; g < 2; g++) {
            const int j = tid + 128 * g;
            const int e = j >> 4, seg = j & 15;
            *(uint4*)(Vh + e * 136 + seg * 8) = *(const uint4*)(vhg + (size_t)e * NN + t0 + seg * 8);
        }
        __syncthreads();

        // ---- QK: 3 compensated MMAs per n-block ----
        float S[16][4];
        #pragma unroll
        for (int n = 0; n < 16; n++)
            #pragma unroll
            for (int i = 0; i < 4; i++) S[n][i] = 0.f;

        #pragma unroll
        for (int n = 0; n < 16; n++) {
            const __half* kb = Ksm + (n * 8 + lq) * 40 + lc * 2;
            const uint32_t bh0 = *(const uint32_t*)kb;
            const uint32_t bh1 = *(const uint32_t*)(kb + 8);
            const uint32_t bl0 = *(const uint32_t*)(kb + 16);
            const uint32_t bl1 = *(const uint32_t*)(kb + 24);
            mma_f16(S[n], qh, bh0, bh1);
            mma_f16(S[n], ql, bh0, bh1);
            mma_f16(S[n], qh, bl0, bl1);
        }

        // ---- softmax (rows lq, lq+8); exp via f16x2 MUFU ----
        float cm0 = -1e30f, cm1 = -1e30f;
        #pragma unroll
        for (int n = 0; n < 16; n++) {
            cm0 = fmaxf(cm0, fmaxf(S[n][0], S[n][1]));
            cm1 = fmaxf(cm1, fmaxf(S[n][2], S[n][3]));
        }
        {
            const float mn0 = fmaxf(mr[0], qmax(cm0));
            const float c0 = ex2f_fast(mr[0] - mn0);
            mr[0] = mn0; lrow[0] *= c0;
            const float mn1 = fmaxf(mr[1], qmax(cm1));
            const float c1 = ex2f_fast(mr[1] - mn1);
            mr[1] = mn1; lrow[1] *= c1;
            #pragma unroll
            for (int nb = 0; nb < 2; nb++) {
                o[nb][0] *= c0; o[nb][1] *= c0;
                o[nb][2] *= c1; o[nb][3] *= c1;
            }
        }
        float rs0 = 0.f, rs1 = 0.f;
        #pragma unroll
        for (int n = 0; n < 16; n++) {
            const uint32_t p01 = ex2_h2(cvt_h2(S[n][0] - mr[0], S[n][1] - mr[0]));
            const uint32_t p23 = ex2_h2(cvt_h2(S[n][2] - mr[1], S[n][3] - mr[1]));
            const float2 f01 = h2_to_f2(p01);
            const float2 f23 = h2_to_f2(p23);
            rs0 += f01.x + f01.y;
            rs1 += f23.x + f23.y;
            S[n][0] = __uint_as_float(p01);  // PV A-frag: keys (2lc,2lc+1), row lq
            S[n][1] = __uint_as_float(p23);  // row lq+8
        }
        lrow[0] += qsum(rs0);
        lrow[1] += qsum(rs1);

        // ---- PV ----
        #pragma unroll
        for (int kb = 0; kb < 8; kb++) {
            const uint32_t ah4[4] = {
                __float_as_uint(S[2*kb][0]),   __float_as_uint(S[2*kb][1]),
                __float_as_uint(S[2*kb+1][0]), __float_as_uint(S[2*kb+1][1])
            };
            #pragma unroll
            for (int nb = 0; nb < 2; nb++) {
                const __half* vb = Vh + (nb * 8 + lq) * 136 + kb * 16 + lc * 2;
                const uint32_t b0 = *(const uint32_t*)vb;
                const uint32_t b1 = *(const uint32_t*)(vb + 8);
                mma_f16(o[nb], ah4, b0, b1);
            }
        }
    }

    // ---- fused output projection epilogue ----
    const int b = bh >> 3, hh = bh & 7;
    __syncthreads();
    float* Wos = (float*)Ksm;                 // [16][17] fp32, reuses K smem
    if (tid < 64) {
        const int c = tid >> 2, eq = (tid & 3) * 4;
        const float4 w = *(const float4*)(Wo + c * 128 + hh * 16 + eq);
        Wos[c * 17 + eq + 0] = w.x; Wos[c * 17 + eq + 1] = w.y;
        Wos[c * 17 + eq + 2] = w.z; Wos[c * 17 + eq + 3] = w.w;
    }
    __syncthreads();

    const float inv0 = 1.0f / lrow[0];
    const float inv1 = 1.0f / lrow[1];
    // row rA = qrow0+lq owns e = {2lc, 2lc+1, 8+2lc, 8+2lc+1}; row rA+8 likewise
    const float a0 = o[0][0] * inv0, a1 = o[0][1] * inv0;
    const float a2 = o[1][0] * inv0, a3 = o[1][1] * inv0;
    const float b0v = o[0][2] * inv1, b1v = o[0][3] * inv1;
    const float b2v = o[1][2] * inv1, b3v = o[1][3] * inv1;
    const int e0 = lc * 2;
    const int rA = qrow0 + lq;
    float* oA = out + (size_t)(b * NN + rA) * 16;
    float* oB = oA + 8 * 16;
    #pragma unroll
    for (int c = 0; c < 16; c++) {
        const float w0 = Wos[c * 17 + e0],     w1 = Wos[c * 17 + e0 + 1];
        const float w2 = Wos[c * 17 + e0 + 8], w3 = Wos[c * 17 + e0 + 9];
        float va = a0 * w0;
        va = fmaf(a1, w1, va); va = fmaf(a2, w2, va); va = fmaf(a3, w3, va);
        float vb = b0v * w0;
        vb = fmaf(b1v, w1, vb); vb = fmaf(b2v, w2, vb); vb = fmaf(b3v, w3, vb);
        redg_f32(oA + c, va);
        redg_f32(oB + c, vb);
    }
}

// ---------------- launcher ----------------
extern "C" void kernel_launch(void* const* d_in, const int* in_sizes, int n_in,
                              void* d_out, int out_size)
{
    const float* query = (const float*)d_in[0];
    const float* key   = (const float*)d_in[1];
    const float* value = (const float*)d_in[2];
    const float* Wq    = (const float*)d_in[3];
    const float* bq    = (const float*)d_in[4];
    const float* Wk    = (const float*)d_in[5];
    const float* bk    = (const float*)d_in[6];
    const float* Wv    = (const float*)d_in[7];
    const float* bv    = (const float*)d_in[8];
    const float* Wo    = (const float*)d_in[9];
    const float* bo    = (const float*)d_in[10];
    float* out = (float*)d_out;

    const float alpha_q = 0.25f * 1.4426950408889634f;

    prep_kernel<<<896, 128>>>(value, Wv, bv, Wq, Wk, bo, out);
    projqk_mma_kernel<<<dim3(128, 2), 256>>>(query, key, bq, bk, alpha_q);
    attn_mma_kernel<<<BHN * 32, 128>>>(Wo, out);
}

// round 13
// speedup vs baseline: 1.0995x; 1.0995x over previous
#include <cuda_runtime.h>
#include <cuda_fp16.h>
#include <cstdint>

#define BB 4
#define HH 8
#define NN 2048
#define BHN (BB*HH)
#define MROWS (BB*NN)

// ---------------- scratch (static device, no allocs) ----------------
__device__ __half g_q16[BHN * NN * 32];   // [bh][n][qhi16|qlo16], 0.25*log2e folded
__device__ __half g_k16[BHN * NN * 32];   // [bh][n][khi16|klo16]
__device__ __half g_vh16[BHN * 16 * NN];  // [bh][e][n]  V^T (fp16-rn)
__device__ __half g_ctx16[MROWS * 128];   // [b*N+n][h*16+e]  fp16
__device__ __half g_Wh[2 * 128 * 128];    // W hi: [q|k][c][k]
__device__ __half g_Wl[2 * 128 * 128];    // W lo residual

// ---------------- helpers ----------------
__device__ __forceinline__ float ex2f_fast(float x) {
    float y; asm("ex2.approx.ftz.f32 %0, %1;" : "=f"(y) : "f"(x)); return y;
}
__device__ __forceinline__ uint32_t ex2_h2(uint32_t x) {
    uint32_t y; asm("ex2.approx.f16x2 %0, %1;" : "=r"(y) : "r"(x)); return y;
}
__device__ __forceinline__ float dot4acc(float4 a, float4 b, float t) {
    t = fmaf(a.x, b.x, t); t = fmaf(a.y, b.y, t);
    t = fmaf(a.z, b.z, t); t = fmaf(a.w, b.w, t);
    return t;
}
__device__ __forceinline__ float qmax(float v) {
    v = fmaxf(v, __shfl_xor_sync(0xFFFFFFFFu, v, 1));
    v = fmaxf(v, __shfl_xor_sync(0xFFFFFFFFu, v, 2));
    return v;
}
__device__ __forceinline__ float qsum(float v) {
    v += __shfl_xor_sync(0xFFFFFFFFu, v, 1);
    v += __shfl_xor_sync(0xFFFFFFFFu, v, 2);
    return v;
}
__device__ __forceinline__ void mma_f16(float* d, const uint32_t* a,
                                        uint32_t b0, uint32_t b1) {
    asm volatile(
        "mma.sync.aligned.m16n8k16.row.col.f32.f16.f16.f32 "
        "{%0,%1,%2,%3}, {%4,%5,%6,%7}, {%8,%9}, {%0,%1,%2,%3};"
        : "+f"(d[0]), "+f"(d[1]), "+f"(d[2]), "+f"(d[3])
        : "r"(a[0]), "r"(a[1]), "r"(a[2]), "r"(a[3]), "r"(b0), "r"(b1));
}
// packs: low half <- lo, high half <- hi
__device__ __forceinline__ uint32_t cvt_h2(float lo, float hi) {
    uint32_t r;
    asm("cvt.rn.f16x2.f32 %0, %1, %2;" : "=r"(r) : "f"(hi), "f"(lo));
    return r;
}
__device__ __forceinline__ float2 h2_to_f2(uint32_t u) {
    return __half22float2(*reinterpret_cast<__half2*>(&u));
}

// ---------------- V projection + transpose (fp16) + W hi/lo prep (fused) ----------------
// blocks [0,512): projvt; blocks [512,768): Wq/Wk split.
__global__ void __launch_bounds__(128) projvt_prepw_kernel(
    const float* __restrict__ value, const float* __restrict__ Wv,
    const float* __restrict__ bv,
    const float* __restrict__ Wq, const float* __restrict__ Wk)
{
    if (blockIdx.x >= 512) {
        const int idx = (blockIdx.x - 512) * 128 + threadIdx.x;  // 0..32767
        const int m = idx >> 14, rest = idx & 16383;
        const float x = (m ? Wk : Wq)[rest];
        const __half hi = __float2half_rn(x);
        g_Wh[idx] = hi;
        g_Wl[idx] = __float2half_rn(x - __half2float(hi));
        return;
    }
    __shared__ float Wsm[16][17];
    __shared__ float bsm[16];
    __shared__ __half thi[16][128];
    const int bh = blockIdx.x >> 4, nt = blockIdx.x & 15;
    const int b = bh >> 3, h = bh & 7;
    const int t = threadIdx.x;
    if (t < 16) bsm[t] = bv[h * 16 + t];
    for (int i = t; i < 256; i += 128)
        Wsm[i >> 4][i & 15] = Wv[(h * 16 + (i >> 4)) * 16 + (i & 15)];
    __syncthreads();
    const int n = nt * 128 + t;
    const float4* a = (const float4*)(value + ((size_t)(b * NN + n) << 4));
    const float4 a0 = a[0], a1 = a[1], a2 = a[2], a3 = a[3];
    const float av[16] = {a0.x,a0.y,a0.z,a0.w, a1.x,a1.y,a1.z,a1.w,
                          a2.x,a2.y,a2.z,a2.w, a3.x,a3.y,a3.z,a3.w};
    #pragma unroll
    for (int e = 0; e < 16; e++) {
        float acc = bsm[e];
        #pragma unroll
        for (int k = 0; k < 16; k++) acc = fmaf(av[k], Wsm[e][k], acc);
        thi[e][t] = __float2half_rn(acc);
    }
    __syncthreads();
    for (int i = t; i < 2048; i += 128) {
        const int e = i >> 7, j = i & 127;
        g_vh16[((size_t)bh * 16 + e) * NN + nt * 128 + j] = thi[e][j];
    }
}

// ---------------- Q/K projection on tensor cores ----------------
__global__ void __launch_bounds__(256) projqk_mma_kernel(
    const float* __restrict__ Aq, const float* __restrict__ Ak,
    const float* __restrict__ bq, const float* __restrict__ bk, float alpha_q)
{
    const bool is_k = (blockIdx.y != 0);
    const float* A    = is_k ? Ak : Aq;
    const float* bias = is_k ? bk : bq;
    const __half* Wh  = g_Wh + (is_k ? 16384 : 0);
    const __half* Wl  = g_Wl + (is_k ? 16384 : 0);
    __half* outp      = is_k ? g_k16 : g_q16;
    const float alpha = is_k ? 1.0f : alpha_q;

    const int tid = threadIdx.x, lane = tid & 31, wid = tid >> 5;
    const int rg = wid >> 1, cg = wid & 1;
    const int lq = lane >> 2, lc = lane & 3;
    const int r0 = blockIdx.x * 64 + rg * 16;
    const int c0 = cg * 64;

    uint32_t ah[8][4], al[8][4];
    {
        const float* Ar0 = A + (size_t)(r0 + lq) * 128;
        const float* Ar1 = Ar0 + 8 * 128;
        #pragma unroll
        for (int ks = 0; ks < 8; ks++) {
            const int k0 = ks * 16 + lc * 2;
            float2 f0 = *(const float2*)(Ar0 + k0);
            float2 f1 = *(const float2*)(Ar1 + k0);
            float2 f2 = *(const float2*)(Ar0 + k0 + 8);
            float2 f3 = *(const float2*)(Ar1 + k0 + 8);
            ah[ks][0] = cvt_h2(f0.x, f0.y);
            ah[ks][1] = cvt_h2(f1.x, f1.y);
            ah[ks][2] = cvt_h2(f2.x, f2.y);
            ah[ks][3] = cvt_h2(f3.x, f3.y);
            float2 h0 = h2_to_f2(ah[ks][0]), h1 = h2_to_f2(ah[ks][1]);
            float2 h2 = h2_to_f2(ah[ks][2]), h3 = h2_to_f2(ah[ks][3]);
            al[ks][0] = cvt_h2(f0.x - h0.x, f0.y - h0.y);
            al[ks][1] = cvt_h2(f1.x - h1.x, f1.y - h1.y);
            al[ks][2] = cvt_h2(f2.x - h2.x, f2.y - h2.y);
            al[ks][3] = cvt_h2(f3.x - h3.x, f3.y - h3.y);
        }
    }

    float D[8][4];
    #pragma unroll
    for (int nb = 0; nb < 8; nb++)
        #pragma unroll
        for (int i = 0; i < 4; i++) D[nb][i] = 0.f;

    #pragma unroll
    for (int nb = 0; nb < 8; nb++) {
        const int c = c0 + nb * 8 + lq;
        const __half* whp = Wh + (size_t)c * 128;
        const __half* wlp = Wl + (size_t)c * 128;
        #pragma unroll
        for (int ks = 0; ks < 8; ks++) {
            const int k0 = ks * 16 + lc * 2;
            const uint32_t bh0 = *(const uint32_t*)(whp + k0);
            const uint32_t bh1 = *(const uint32_t*)(whp + k0 + 8);
            const uint32_t bl0 = *(const uint32_t*)(wlp + k0);
            const uint32_t bl1 = *(const uint32_t*)(wlp + k0 + 8);
            mma_f16(D[nb], ah[ks], bh0, bh1);
            mma_f16(D[nb], al[ks], bh0, bh1);
            mma_f16(D[nb], ah[ks], bl0, bl1);
        }
    }

    #pragma unroll
    for (int nb = 0; nb < 8; nb++) {
        const int ce = c0 + nb * 8 + lc * 2;
        const float2 bb = *(const float2*)(bias + ce);
        const int h = ce >> 4, d = ce & 15;
        #pragma unroll
        for (int rr = 0; rr < 2; rr++) {
            const int row = r0 + lq + rr * 8;
            const int b = row >> 11, n = row & 2047;
            __half* base = outp + ((size_t)((b * 8 + h) * 2048 + n)) * 32;
            const float x0 = (D[nb][2*rr + 0] + bb.x) * alpha;
            const float x1 = (D[nb][2*rr + 1] + bb.y) * alpha;
            const uint32_t hi2 = cvt_h2(x0, x1);
            const float2 hf = h2_to_f2(hi2);
            const uint32_t lo2 = cvt_h2(x0 - hf.x, x1 - hf.y);
            *(uint32_t*)(base + d)      = hi2;
            *(uint32_t*)(base + 16 + d) = lo2;
        }
    }
}

// ---------------- fp16 mma.sync flash attention ----------------
// 1024 CTAs = 32 bh x 32 q-tiles of 64 rows; 4 warps; warp owns 16 q-rows; 4 CTAs/SM.
// Softmax exp via ex2.approx.f16x2 — one MUFU per 2 scores; output IS the PV A-fragment.
__global__ void __launch_bounds__(128, 4) attn_mma_kernel()
{
    __shared__ __align__(16) __half Ksm[128 * 40];   // [key][hi16|lo16|pad8]
    __shared__ __align__(16) __half Vh[16 * 136];    // [e][key]

    const int tid = threadIdx.x, lane = tid & 31, wid = tid >> 5;
    const int bh = blockIdx.x >> 5, qt = blockIdx.x & 31;
    const int qrow0 = qt * 64 + wid * 16;
    const int lq = lane >> 2;
    const int lc = lane & 3;

    uint32_t qh[4], ql[4];
    {
        const __half* p0 = g_q16 + ((size_t)(bh * NN + qrow0 + lq)) * 32 + lc * 2;
        qh[0] = *(const uint32_t*)(p0);
        qh[1] = *(const uint32_t*)(p0 + 256);
        qh[2] = *(const uint32_t*)(p0 + 8);
        qh[3] = *(const uint32_t*)(p0 + 264);
        ql[0] = *(const uint32_t*)(p0 + 16);
        ql[1] = *(const uint32_t*)(p0 + 272);
        ql[2] = *(const uint32_t*)(p0 + 24);
        ql[3] = *(const uint32_t*)(p0 + 280);
    }

    float mr[2] = {-1e30f, -1e30f}, lrow[2] = {0.f, 0.f};
    float o[2][4];
    #pragma unroll
    for (int nb = 0; nb < 2; nb++)
        #pragma unroll
        for (int i = 0; i < 4; i++) o[nb][i] = 0.f;

    const uint4* kg = (const uint4*)(g_k16 + ((size_t)bh * NN) * 32);
    const __half* vhg = g_vh16 + (size_t)bh * 16 * NN;

    for (int t0 = 0; t0 < NN; t0 += 128) {
        __syncthreads();
        #pragma unroll
        for (int g = 0; g < 4; g++) {
            const int j = tid + 128 * g;
            const int key = j >> 2, seg = j & 3;
            *(uint4*)(Ksm + key * 40 + seg * 8) = kg[(size_t)t0 * 4 + j];
        }
        #pragma unroll
        for (int g = 0; g < 2; g++) {
            const int j = tid + 128 * g;
            const int e = j >> 4, seg = j & 15;
            *(uint4*)(Vh + e * 136 + seg * 8) = *(const uint4*)(vhg + (size_t)e * NN + t0 + seg * 8);
        }
        __syncthreads();

        // ---- QK: 3 compensated MMAs per n-block ----
        float S[16][4];
        #pragma unroll
        for (int n = 0; n < 16; n++)
            #pragma unroll
            for (int i = 0; i < 4; i++) S[n][i] = 0.f;

        #pragma unroll
        for (int n = 0; n < 16; n++) {
            const __half* kb = Ksm + (n * 8 + lq) * 40 + lc * 2;
            const uint32_t bh0 = *(const uint32_t*)kb;
            const uint32_t bh1 = *(const uint32_t*)(kb + 8);
            const uint32_t bl0 = *(const uint32_t*)(kb + 16);
            const uint32_t bl1 = *(const uint32_t*)(kb + 24);
            mma_f16(S[n], qh, bh0, bh1);
            mma_f16(S[n], ql, bh0, bh1);
            mma_f16(S[n], qh, bl0, bl1);
        }

        // ---- softmax (rows lq, lq+8); exp on MUFU f16x2 ----
        float cm0 = -1e30f, cm1 = -1e30f;
        #pragma unroll
        for (int n = 0; n < 16; n++) {
            cm0 = fmaxf(cm0, fmaxf(S[n][0], S[n][1]));
            cm1 = fmaxf(cm1, fmaxf(S[n][2], S[n][3]));
        }
        {
            const float mn0 = fmaxf(mr[0], qmax(cm0));
            const float c0 = ex2f_fast(mr[0] - mn0);
            mr[0] = mn0; lrow[0] *= c0;
            const float mn1 = fmaxf(mr[1], qmax(cm1));
            const float c1 = ex2f_fast(mr[1] - mn1);
            mr[1] = mn1; lrow[1] *= c1;
            #pragma unroll
            for (int nb = 0; nb < 2; nb++) {
                o[nb][0] *= c0; o[nb][1] *= c0;
                o[nb][2] *= c1; o[nb][3] *= c1;
            }
        }
        float rs0 = 0.f, rs1 = 0.f;
        #pragma unroll
        for (int n = 0; n < 16; n++) {
            const uint32_t p01 = ex2_h2(cvt_h2(S[n][0] - mr[0], S[n][1] - mr[0]));
            const uint32_t p23 = ex2_h2(cvt_h2(S[n][2] - mr[1], S[n][3] - mr[1]));
            const float2 f01 = h2_to_f2(p01);
            const float2 f23 = h2_to_f2(p23);
            rs0 += f01.x + f01.y;
            rs1 += f23.x + f23.y;
            S[n][0] = __uint_as_float(p01);  // PV A-frag: keys (2lc,2lc+1), row lq
            S[n][1] = __uint_as_float(p23);  // row lq+8
        }
        lrow[0] += qsum(rs0);
        lrow[1] += qsum(rs1);

        // ---- PV ----
        #pragma unroll
        for (int kb = 0; kb < 8; kb++) {
            const uint32_t ah4[4] = {
                __float_as_uint(S[2*kb][0]),   __float_as_uint(S[2*kb][1]),
                __float_as_uint(S[2*kb+1][0]), __float_as_uint(S[2*kb+1][1])
            };
            #pragma unroll
            for (int nb = 0; nb < 2; nb++) {
                const __half* vb = Vh + (nb * 8 + lq) * 136 + kb * 16 + lc * 2;
                const uint32_t b0 = *(const uint32_t*)vb;
                const uint32_t b1 = *(const uint32_t*)(vb + 8);
                mma_f16(o[nb], ah4, b0, b1);
            }
        }
    }

    // ---- epilogue: fp16 ctx ----
    const float inv0 = 1.0f / lrow[0];
    const float inv1 = 1.0f / lrow[1];
    const int b = bh >> 3, hh = bh & 7;
    const int rA = qrow0 + lq;
    #pragma unroll
    for (int nb = 0; nb < 2; nb++) {
        const int e0 = nb * 8 + lc * 2;
        __half* pA = g_ctx16 + ((size_t)(b * NN + rA)) * 128 + hh * 16 + e0;
        __half* pB = pA + 8 * 128;
        *(uint32_t*)pA = cvt_h2(o[nb][0] * inv0, o[nb][1] * inv0);
        *(uint32_t*)pB = cvt_h2(o[nb][2] * inv1, o[nb][3] * inv1);
    }
}

// ---------------- output projection (fp16 ctx in) ----------------
__global__ void __launch_bounds__(256) outproj_kernel(
    const float* __restrict__ Wo, const float* __restrict__ bo,
    float* __restrict__ out)
{
    __shared__ float Cs[32][128];
    __shared__ float Ws[16][132];
    const int r0 = blockIdx.x * 32;
    const uint32_t* cg16 = (const uint32_t*)(g_ctx16 + ((size_t)r0 << 7));
    float2* csv = (float2*)&Cs[0][0];
    #pragma unroll
    for (int i = 0; i < 8; i++) {
        const int idx = threadIdx.x + 256 * i;
        csv[idx] = h2_to_f2(cg16[idx]);
    }
    for (int i = threadIdx.x; i < 2048; i += 256) Ws[i >> 7][i & 127] = Wo[i];
    __syncthreads();
    const int r = threadIdx.x >> 4, c = threadIdx.x & 15;
    float acc0 = bo[c], acc1 = bo[c];
    #pragma unroll
    for (int kk = 0; kk < 128; kk += 4) {
        float4 w = *(const float4*)&Ws[c][kk];
        float4 a0 = *(const float4*)&Cs[r][kk];
        float4 a1 = *(const float4*)&Cs[r + 16][kk];
        acc0 = dot4acc(a0, w, acc0);
        acc1 = dot4acc(a1, w, acc1);
    }
    out[((size_t)(r0 + r) << 4) + c]      = acc0;
    out[((size_t)(r0 + r + 16) << 4) + c] = acc1;
}

// ---------------- launcher ----------------
extern "C" void kernel_launch(void* const* d_in, const int* in_sizes, int n_in,
                              void* d_out, int out_size)
{
    const float* query = (const float*)d_in[0];
    const float* key   = (const float*)d_in[1];
    const float* value = (const float*)d_in[2];
    const float* Wq    = (const float*)d_in[3];
    const float* bq    = (const float*)d_in[4];
    const float* Wk    = (const float*)d_in[5];
    const float* bk    = (const float*)d_in[6];
    const float* Wv    = (const float*)d_in[7];
    const float* bv    = (const float*)d_in[8];
    const float* Wo    = (const float*)d_in[9];
    const float* bo    = (const float*)d_in[10];
    float* out = (float*)d_out;

    const float alpha_q = 0.25f * 1.4426950408889634f;

    projvt_prepw_kernel<<<768, 128>>>(value, Wv, bv, Wq, Wk);
    projqk_mma_kernel<<<dim3(128, 2), 256>>>(query, key, bq, bk, alpha_q);
    attn_mma_kernel<<<BHN * 32, 128>>>();
    outproj_kernel<<<MROWS / 32, 256>>>(Wo, bo, out);
}

// round 14
// speedup vs baseline: 1.1689x; 1.0631x over previous
#include <cuda_runtime.h>
#include <cuda_fp16.h>
#include <cstdint>

#define BB 4
#define HH 8
#define NN 2048
#define BHN (BB*HH)
#define MROWS (BB*NN)

// ---------------- scratch (static device, no allocs) ----------------
__device__ __half g_q16[BHN * NN * 32];   // [bh][n][qhi16|qlo16], 0.25*log2e folded
__device__ __half g_k16[BHN * NN * 32];   // [bh][n][khi16|klo16]
__device__ __half g_vh16[BHN * 16 * NN];  // [bh][e][n]  V^T (fp16-rn)
__device__ __half g_Wh[2 * 128 * 128];    // Wq/Wk hi: [q|k][c][k]
__device__ __half g_Wl[2 * 128 * 128];    // Wq/Wk lo residual
__device__ __half g_Woh[HH * 16 * 16];    // Wo hi: [h][c][e]
__device__ __half g_Wol[HH * 16 * 16];    // Wo lo residual

// ---------------- helpers ----------------
__device__ __forceinline__ float ex2f_fast(float x) {
    float y; asm("ex2.approx.ftz.f32 %0, %1;" : "=f"(y) : "f"(x)); return y;
}
__device__ __forceinline__ float qmax(float v) {
    v = fmaxf(v, __shfl_xor_sync(0xFFFFFFFFu, v, 1));
    v = fmaxf(v, __shfl_xor_sync(0xFFFFFFFFu, v, 2));
    return v;
}
__device__ __forceinline__ float qsum(float v) {
    v += __shfl_xor_sync(0xFFFFFFFFu, v, 1);
    v += __shfl_xor_sync(0xFFFFFFFFu, v, 2);
    return v;
}
__device__ __forceinline__ void mma_f16(float* d, const uint32_t* a,
                                        uint32_t b0, uint32_t b1) {
    asm volatile(
        "mma.sync.aligned.m16n8k16.row.col.f32.f16.f16.f32 "
        "{%0,%1,%2,%3}, {%4,%5,%6,%7}, {%8,%9}, {%0,%1,%2,%3};"
        : "+f"(d[0]), "+f"(d[1]), "+f"(d[2]), "+f"(d[3])
        : "r"(a[0]), "r"(a[1]), "r"(a[2]), "r"(a[3]), "r"(b0), "r"(b1));
}
// packs: low half <- lo, high half <- hi
__device__ __forceinline__ uint32_t cvt_h2(float lo, float hi) {
    uint32_t r;
    asm("cvt.rn.f16x2.f32 %0, %1, %2;" : "=r"(r) : "f"(hi), "f"(lo));
    return r;
}
__device__ __forceinline__ float2 h2_to_f2(uint32_t u) {
    return __half22float2(*reinterpret_cast<__half2*>(&u));
}
__device__ __forceinline__ void redg_f32(float* p, float v) {
    asm volatile("red.global.add.f32 [%0], %1;" :: "l"(p), "f"(v) : "memory");
}

// ---------------- kernel 1: V proj+transpose, W splits, out<-bias ----------------
// blocks [0,512): projvt; [512,768): Wq/Wk split; [768,896): out init; [896,912): Wo split.
__global__ void __launch_bounds__(128) prep_kernel(
    const float* __restrict__ value, const float* __restrict__ Wv,
    const float* __restrict__ bv,
    const float* __restrict__ Wq, const float* __restrict__ Wk,
    const float* __restrict__ Wo, const float* __restrict__ bo,
    float* __restrict__ out)
{
    if (blockIdx.x >= 896) {
        const int idx = (blockIdx.x - 896) * 128 + threadIdx.x;  // 0..2047
        const int c = idx >> 7, rest = idx & 127;
        const int hh = rest >> 4, e = rest & 15;
        const float x = Wo[c * 128 + rest];
        const __half hi = __float2half_rn(x);
        g_Woh[hh * 256 + c * 16 + e] = hi;
        g_Wol[hh * 256 + c * 16 + e] = __float2half_rn(x - __half2float(hi));
        return;
    }
    if (blockIdx.x >= 768) {
        const int i = ((blockIdx.x - 768) * 128 + threadIdx.x) * 8;  // 8-aligned
        const int c = i & 15;                                        // 0 or 8
        const float4 b0 = *(const float4*)(bo + c);
        const float4 b1 = *(const float4*)(bo + c + 4);
        *(float4*)(out + i)     = b0;
        *(float4*)(out + i + 4) = b1;
        return;
    }
    if (blockIdx.x >= 512) {
        const int idx = (blockIdx.x - 512) * 128 + threadIdx.x;  // 0..32767
        const int m = idx >> 14, rest = idx & 16383;
        const float x = (m ? Wk : Wq)[rest];
        const __half hi = __float2half_rn(x);
        g_Wh[idx] = hi;
        g_Wl[idx] = __float2half_rn(x - __half2float(hi));
        return;
    }
    __shared__ float Wsm[16][17];
    __shared__ float bsm[16];
    __shared__ __half thi[16][128];
    const int bh = blockIdx.x >> 4, nt = blockIdx.x & 15;
    const int b = bh >> 3, h = bh & 7;
    const int t = threadIdx.x;
    if (t < 16) bsm[t] = bv[h * 16 + t];
    for (int i = t; i < 256; i += 128)
        Wsm[i >> 4][i & 15] = Wv[(h * 16 + (i >> 4)) * 16 + (i & 15)];
    __syncthreads();
    const int n = nt * 128 + t;
    const float4* a = (const float4*)(value + ((size_t)(b * NN + n) << 4));
    const float4 a0 = a[0], a1 = a[1], a2 = a[2], a3 = a[3];
    const float av[16] = {a0.x,a0.y,a0.z,a0.w, a1.x,a1.y,a1.z,a1.w,
                          a2.x,a2.y,a2.z,a2.w, a3.x,a3.y,a3.z,a3.w};
    #pragma unroll
    for (int e = 0; e < 16; e++) {
        float acc = bsm[e];
        #pragma unroll
        for (int k = 0; k < 16; k++) acc = fmaf(av[k], Wsm[e][k], acc);
        thi[e][t] = __float2half_rn(acc);
    }
    __syncthreads();
    for (int i = t; i < 2048; i += 128) {
        const int e = i >> 7, j = i & 127;
        g_vh16[((size_t)bh * 16 + e) * NN + nt * 128 + j] = thi[e][j];
    }
}

// ---------------- Q/K projection on tensor cores ----------------
__global__ void __launch_bounds__(256) projqk_mma_kernel(
    const float* __restrict__ Aq, const float* __restrict__ Ak,
    const float* __restrict__ bq, const float* __restrict__ bk, float alpha_q)
{
    const bool is_k = (blockIdx.y != 0);
    const float* A    = is_k ? Ak : Aq;
    const float* bias = is_k ? bk : bq;
    const __half* Wh  = g_Wh + (is_k ? 16384 : 0);
    const __half* Wl  = g_Wl + (is_k ? 16384 : 0);
    __half* outp      = is_k ? g_k16 : g_q16;
    const float alpha = is_k ? 1.0f : alpha_q;

    const int tid = threadIdx.x, lane = tid & 31, wid = tid >> 5;
    const int rg = wid >> 1, cg = wid & 1;
    const int lq = lane >> 2, lc = lane & 3;
    const int r0 = blockIdx.x * 64 + rg * 16;
    const int c0 = cg * 64;

    uint32_t ah[8][4], al[8][4];
    {
        const float* Ar0 = A + (size_t)(r0 + lq) * 128;
        const float* Ar1 = Ar0 + 8 * 128;
        #pragma unroll
        for (int ks = 0; ks < 8; ks++) {
            const int k0 = ks * 16 + lc * 2;
            float2 f0 = *(const float2*)(Ar0 + k0);
            float2 f1 = *(const float2*)(Ar1 + k0);
            float2 f2 = *(const float2*)(Ar0 + k0 + 8);
            float2 f3 = *(const float2*)(Ar1 + k0 + 8);
            ah[ks][0] = cvt_h2(f0.x, f0.y);
            ah[ks][1] = cvt_h2(f1.x, f1.y);
            ah[ks][2] = cvt_h2(f2.x, f2.y);
            ah[ks][3] = cvt_h2(f3.x, f3.y);
            float2 h0 = h2_to_f2(ah[ks][0]), h1 = h2_to_f2(ah[ks][1]);
            float2 h2 = h2_to_f2(ah[ks][2]), h3 = h2_to_f2(ah[ks][3]);
            al[ks][0] = cvt_h2(f0.x - h0.x, f0.y - h0.y);
            al[ks][1] = cvt_h2(f1.x - h1.x, f1.y - h1.y);
            al[ks][2] = cvt_h2(f2.x - h2.x, f2.y - h2.y);
            al[ks][3] = cvt_h2(f3.x - h3.x, f3.y - h3.y);
        }
    }

    float D[8][4];
    #pragma unroll
    for (int nb = 0; nb < 8; nb++)
        #pragma unroll
        for (int i = 0; i < 4; i++) D[nb][i] = 0.f;

    #pragma unroll
    for (int nb = 0; nb < 8; nb++) {
        const int c = c0 + nb * 8 + lq;
        const __half* whp = Wh + (size_t)c * 128;
        const __half* wlp = Wl + (size_t)c * 128;
        #pragma unroll
        for (int ks = 0; ks < 8; ks++) {
            const int k0 = ks * 16 + lc * 2;
            const uint32_t bh0 = *(const uint32_t*)(whp + k0);
            const uint32_t bh1 = *(const uint32_t*)(whp + k0 + 8);
            const uint32_t bl0 = *(const uint32_t*)(wlp + k0);
            const uint32_t bl1 = *(const uint32_t*)(wlp + k0 + 8);
            mma_f16(D[nb], ah[ks], bh0, bh1);
            mma_f16(D[nb], al[ks], bh0, bh1);
            mma_f16(D[nb], ah[ks], bl0, bl1);
        }
    }

    #pragma unroll
    for (int nb = 0; nb < 8; nb++) {
        const int ce = c0 + nb * 8 + lc * 2;
        const float2 bb = *(const float2*)(bias + ce);
        const int h = ce >> 4, d = ce & 15;
        #pragma unroll
        for (int rr = 0; rr < 2; rr++) {
            const int row = r0 + lq + rr * 8;
            const int b = row >> 11, n = row & 2047;
            __half* base = outp + ((size_t)((b * 8 + h) * 2048 + n)) * 32;
            const float x0 = (D[nb][2*rr + 0] + bb.x) * alpha;
            const float x1 = (D[nb][2*rr + 1] + bb.y) * alpha;
            const uint32_t hi2 = cvt_h2(x0, x1);
            const float2 hf = h2_to_f2(hi2);
            const uint32_t lo2 = cvt_h2(x0 - hf.x, x1 - hf.y);
            *(uint32_t*)(base + d)      = hi2;
            *(uint32_t*)(base + 16 + d) = lo2;
        }
    }
}

// ---------------- fp16 mma.sync flash attention + HMMA-fused out projection ----------------
// 1024 CTAs = 32 bh x 32 q-tiles of 64 rows; 4 warps; warp owns 16 q-rows; 4 CTAs/SM.
// Epilogue: ctx fragment @ Wo_h^T via 4 MMAs (hi/lo compensated), 8 REDG/thread into out.
__global__ void __launch_bounds__(128, 4) attn_mma_kernel(float* __restrict__ out)
{
    __shared__ __align__(16) __half Ksm[128 * 40];   // [key][hi16|lo16|pad8]
    __shared__ __align__(16) __half Vh[16 * 136];    // [e][key]

    const int tid = threadIdx.x, lane = tid & 31, wid = tid >> 5;
    const int bh = blockIdx.x >> 5, qt = blockIdx.x & 31;
    const int qrow0 = qt * 64 + wid * 16;
    const int lq = lane >> 2;
    const int lc = lane & 3;

    uint32_t qh[4], ql[4];
    {
        const __half* p0 = g_q16 + ((size_t)(bh * NN + qrow0 + lq)) * 32 + lc * 2;
        qh[0] = *(const uint32_t*)(p0);
        qh[1] = *(const uint32_t*)(p0 + 256);
        qh[2] = *(const uint32_t*)(p0 + 8);
        qh[3] = *(const uint32_t*)(p0 + 264);
        ql[0] = *(const uint32_t*)(p0 + 16);
        ql[1] = *(const uint32_t*)(p0 + 272);
        ql[2] = *(const uint32_t*)(p0 + 24);
        ql[3] = *(const uint32_t*)(p0 + 280);
    }

    float mr[2] = {-1e30f, -1e30f}, lrow[2] = {0.f, 0.f};
    float o[2][4];
    #pragma unroll
    for (int nb = 0; nb < 2; nb++)
        #pragma unroll
        for (int i = 0; i < 4; i++) o[nb][i] = 0.f;

    const uint4* kg = (const uint4*)(g_k16 + ((size_t)bh * NN) * 32);
    const __half* vhg = g_vh16 + (size_t)bh * 16 * NN;

    for (int t0 = 0; t0 < NN; t0 += 128) {
        __syncthreads();
        #pragma unroll
        for (int g = 0; g < 4; g++) {
            const int j = tid + 128 * g;
            const int key = j >> 2, seg = j & 3;
            *(uint4*)(Ksm + key * 40 + seg * 8) = kg[(size_t)t0 * 4 + j];
        }
        #pragma unroll
        for (int g = 0; g < 2; g++) {
            const int j = tid + 128 * g;
            const int e = j >> 4, seg = j & 15;
            *(uint4*)(Vh + e * 136 + seg * 8) = *(const uint4*)(vhg + (size_t)e * NN + t0 + seg * 8);
        }
        __syncthreads();

        // ---- QK: 3 compensated MMAs per n-block ----
        float S[16][4];
        #pragma unroll
        for (int n = 0; n < 16; n++)
            #pragma unroll
            for (int i = 0; i < 4; i++) S[n][i] = 0.f;

        #pragma unroll
        for (int n = 0; n < 16; n++) {
            const __half* kb = Ksm + (n * 8 + lq) * 40 + lc * 2;
            const uint32_t bh0 = *(const uint32_t*)kb;
            const uint32_t bh1 = *(const uint32_t*)(kb + 8);
            const uint32_t bl0 = *(const uint32_t*)(kb + 16);
            const uint32_t bl1 = *(const uint32_t*)(kb + 24);
            mma_f16(S[n], qh, bh0, bh1);
            mma_f16(S[n], ql, bh0, bh1);
            mma_f16(S[n], qh, bl0, bl1);
        }

        // ---- softmax (rows lq, lq+8); f32 ex2 (round-11 proven path) ----
        float cm0 = -1e30f, cm1 = -1e30f;
        #pragma unroll
        for (int n = 0; n < 16; n++) {
            cm0 = fmaxf(cm0, fmaxf(S[n][0], S[n][1]));
            cm1 = fmaxf(cm1, fmaxf(S[n][2], S[n][3]));
        }
        {
            const float mn0 = fmaxf(mr[0], qmax(cm0));
            const float c0 = ex2f_fast(mr[0] - mn0);
            mr[0] = mn0; lrow[0] *= c0;
            const float mn1 = fmaxf(mr[1], qmax(cm1));
            const float c1 = ex2f_fast(mr[1] - mn1);
            mr[1] = mn1; lrow[1] *= c1;
            #pragma unroll
            for (int nb = 0; nb < 2; nb++) {
                o[nb][0] *= c0; o[nb][1] *= c0;
                o[nb][2] *= c1; o[nb][3] *= c1;
            }
        }
        float rs0 = 0.f, rs1 = 0.f;
        #pragma unroll
        for (int n = 0; n < 16; n++) {
            const float p0 = ex2f_fast(S[n][0] - mr[0]);
            const float p1 = ex2f_fast(S[n][1] - mr[0]);
            const float p2 = ex2f_fast(S[n][2] - mr[1]);
            const float p3 = ex2f_fast(S[n][3] - mr[1]);
            rs0 += p0 + p1;
            rs1 += p2 + p3;
            S[n][0] = __uint_as_float(cvt_h2(p0, p1));  // PV A-frag: keys (2lc,2lc+1), row lq
            S[n][1] = __uint_as_float(cvt_h2(p2, p3));  // row lq+8
        }
        lrow[0] += qsum(rs0);
        lrow[1] += qsum(rs1);

        // ---- PV ----
        #pragma unroll
        for (int kb = 0; kb < 8; kb++) {
            const uint32_t ah4[4] = {
                __float_as_uint(S[2*kb][0]),   __float_as_uint(S[2*kb][1]),
                __float_as_uint(S[2*kb+1][0]), __float_as_uint(S[2*kb+1][1])
            };
            #pragma unroll
            for (int nb = 0; nb < 2; nb++) {
                const __half* vb = Vh + (nb * 8 + lq) * 136 + kb * 16 + lc * 2;
                const uint32_t b0 = *(const uint32_t*)vb;
                const uint32_t b1 = *(const uint32_t*)(vb + 8);
                mma_f16(o[nb], ah4, b0, b1);
            }
        }
    }

    // ---- fused out projection: ctx-frag @ Wo_h^T (hi/lo compensated) + REDG ----
    const float inv0 = 1.0f / lrow[0];
    const float inv1 = 1.0f / lrow[1];
    const int b = bh >> 3, hh = bh & 7;
    const int rA = qrow0 + lq;

    // A fragment = normalized context rows (lq, lq+8) x e[0..16)
    const uint32_t pa[4] = {
        cvt_h2(o[0][0] * inv0, o[0][1] * inv0),   // row lq,   e = 2lc, 2lc+1
        cvt_h2(o[0][2] * inv1, o[0][3] * inv1),   // row lq+8, e = 2lc, 2lc+1
        cvt_h2(o[1][0] * inv0, o[1][1] * inv0),   // row lq,   e = 8+2lc, 8+2lc+1
        cvt_h2(o[1][2] * inv1, o[1][3] * inv1)    // row lq+8, e = 8+2lc, 8+2lc+1
    };
    const __half* wbh = g_Woh + hh * 256;
    const __half* wbl = g_Wol + hh * 256;
    float d0[4] = {0.f, 0.f, 0.f, 0.f};
    float d1[4] = {0.f, 0.f, 0.f, 0.f};
    {   // MMA0: out cols 0..7 (n = lq -> c = lq)
        const uint32_t b0h = *(const uint32_t*)(wbh + lq * 16 + lc * 2);
        const uint32_t b1h = *(const uint32_t*)(wbh + lq * 16 + lc * 2 + 8);
        const uint32_t b0l = *(const uint32_t*)(wbl + lq * 16 + lc * 2);
        const uint32_t b1l = *(const uint32_t*)(wbl + lq * 16 + lc * 2 + 8);
        mma_f16(d0, pa, b0h, b1h);
        mma_f16(d0, pa, b0l, b1l);
    }
    {   // MMA1: out cols 8..15 (c = 8 + lq)
        const uint32_t b0h = *(const uint32_t*)(wbh + (8 + lq) * 16 + lc * 2);
        const uint32_t b1h = *(const uint32_t*)(wbh + (8 + lq) * 16 + lc * 2 + 8);
        const uint32_t b0l = *(const uint32_t*)(wbl + (8 + lq) * 16 + lc * 2);
        const uint32_t b1l = *(const uint32_t*)(wbl + (8 + lq) * 16 + lc * 2 + 8);
        mma_f16(d1, pa, b0h, b1h);
        mma_f16(d1, pa, b0l, b1l);
    }
    float* oA = out + (size_t)(b * NN + rA) * 16;
    float* oB = oA + 8 * 16;
    redg_f32(oA + 2*lc,     d0[0]); redg_f32(oA + 2*lc + 1,     d0[1]);
    redg_f32(oB + 2*lc,     d0[2]); redg_f32(oB + 2*lc + 1,     d0[3]);
    redg_f32(oA + 8 + 2*lc, d1[0]); redg_f32(oA + 8 + 2*lc + 1, d1[1]);
    redg_f32(oB + 8 + 2*lc, d1[2]); redg_f32(oB + 8 + 2*lc + 1, d1[3]);
}

// ---------------- launcher ----------------
extern "C" void kernel_launch(void* const* d_in, const int* in_sizes, int n_in,
                              void* d_out, int out_size)
{
    const float* query = (const float*)d_in[0];
    const float* key   = (const float*)d_in[1];
    const float* value = (const float*)d_in[2];
    const float* Wq    = (const float*)d_in[3];
    const float* bq    = (const float*)d_in[4];
    const float* Wk    = (const float*)d_in[5];
    const float* bk    = (const float*)d_in[6];
    const float* Wv    = (const float*)d_in[7];
    const float* bv    = (const float*)d_in[8];
    const float* Wo    = (const float*)d_in[9];
    const float* bo    = (const float*)d_in[10];
    float* out = (float*)d_out;

    const float alpha_q = 0.25f * 1.4426950408889634f;

    prep_kernel<<<912, 128>>>(value, Wv, bv, Wq, Wk, Wo, bo, out);
    projqk_mma_kernel<<<dim3(128, 2), 256>>>(query, key, bq, bk, alpha_q);
    attn_mma_kernel<<<BHN * 32, 128>>>(out);
}

// round 15
// speedup vs baseline: 1.1938x; 1.0213x over previous
#include <cuda_runtime.h>
#include <cuda_fp16.h>
#include <cstdint>

#define BB 4
#define HH 8
#define NN 2048
#define BHN (BB*HH)
#define MROWS (BB*NN)

// ---------------- scratch (static device, no allocs) ----------------
__device__ __half g_q16[BHN * NN * 32];   // [bh][n][qhi16|qlo16], 0.25*log2e folded
__device__ __half g_k16[BHN * NN * 32];   // [bh][n][khi16|klo16]
__device__ __half g_vh16[BHN * 16 * NN];  // [bh][e][n]  V^T (fp16-rn)
__device__ __half g_Wh[2 * 128 * 128];    // Wq/Wk hi: [q|k][c][k]
__device__ __half g_Wl[2 * 128 * 128];    // Wq/Wk lo residual
__device__ __half g_Woh[HH * 16 * 16];    // Wo hi: [h][c][e]
__device__ __half g_Wol[HH * 16 * 16];    // Wo lo residual

// ---------------- helpers ----------------
__device__ __forceinline__ float ex2f_fast(float x) {
    float y; asm("ex2.approx.ftz.f32 %0, %1;" : "=f"(y) : "f"(x)); return y;
}
__device__ __forceinline__ float qmax(float v) {
    v = fmaxf(v, __shfl_xor_sync(0xFFFFFFFFu, v, 1));
    v = fmaxf(v, __shfl_xor_sync(0xFFFFFFFFu, v, 2));
    return v;
}
__device__ __forceinline__ void mma_f16(float* d, const uint32_t* a,
                                        uint32_t b0, uint32_t b1) {
    asm volatile(
        "mma.sync.aligned.m16n8k16.row.col.f32.f16.f16.f32 "
        "{%0,%1,%2,%3}, {%4,%5,%6,%7}, {%8,%9}, {%0,%1,%2,%3};"
        : "+f"(d[0]), "+f"(d[1]), "+f"(d[2]), "+f"(d[3])
        : "r"(a[0]), "r"(a[1]), "r"(a[2]), "r"(a[3]), "r"(b0), "r"(b1));
}
// packs: low half <- lo, high half <- hi
__device__ __forceinline__ uint32_t cvt_h2(float lo, float hi) {
    uint32_t r;
    asm("cvt.rn.f16x2.f32 %0, %1, %2;" : "=r"(r) : "f"(hi), "f"(lo));
    return r;
}
__device__ __forceinline__ float2 h2_to_f2(uint32_t u) {
    return __half22float2(*reinterpret_cast<__half2*>(&u));
}
__device__ __forceinline__ void redg_f32(float* p, float v) {
    asm volatile("red.global.add.f32 [%0], %1;" :: "l"(p), "f"(v) : "memory");
}

// ---------------- kernel 1: V proj+transpose, W splits, out<-bias ----------------
// 256 threads. blocks [0,256): projvt (256 rows each); [256,384): Wq/Wk split;
// [384,448): out init; [448,456): Wo split.
__global__ void __launch_bounds__(256) prep_kernel(
    const float* __restrict__ value, const float* __restrict__ Wv,
    const float* __restrict__ bv,
    const float* __restrict__ Wq, const float* __restrict__ Wk,
    const float* __restrict__ Wo, const float* __restrict__ bo,
    float* __restrict__ out)
{
    const int t = threadIdx.x;
    if (blockIdx.x >= 448) {
        const int idx = (blockIdx.x - 448) * 256 + t;   // 0..2047
        const int c = idx >> 7, rest = idx & 127;
        const int hh = rest >> 4, e = rest & 15;
        const float x = Wo[idx];
        const __half hi = __float2half_rn(x);
        g_Woh[hh * 256 + c * 16 + e] = hi;
        g_Wol[hh * 256 + c * 16 + e] = __float2half_rn(x - __half2float(hi));
        return;
    }
    if (blockIdx.x >= 384) {
        const int i = ((blockIdx.x - 384) * 256 + t) * 8;   // 8-aligned
        const int c = i & 15;                               // 0 or 8
        const float4 b0 = *(const float4*)(bo + c);
        const float4 b1 = *(const float4*)(bo + c + 4);
        *(float4*)(out + i)     = b0;
        *(float4*)(out + i + 4) = b1;
        return;
    }
    if (blockIdx.x >= 256) {
        const int idx = (blockIdx.x - 256) * 256 + t;   // 0..32767
        const int m = idx >> 14, rest = idx & 16383;
        const float x = (m ? Wk : Wq)[rest];
        const __half hi = __float2half_rn(x);
        g_Wh[idx] = hi;
        g_Wl[idx] = __float2half_rn(x - __half2float(hi));
        return;
    }
    // projvt: block = (bh, seg of 256 rows)
    __shared__ float Wsm[16][17];
    __shared__ float bsm[16];
    __shared__ __half thi[16][256];
    const int bh = blockIdx.x >> 3, seg = blockIdx.x & 7;
    const int b = bh >> 3, h = bh & 7;
    if (t < 16) bsm[t] = bv[h * 16 + t];
    if (t < 256) Wsm[t >> 4][t & 15] = Wv[(h * 16 + (t >> 4)) * 16 + (t & 15)];
    __syncthreads();
    const int n = seg * 256 + t;
    const float4* a = (const float4*)(value + ((size_t)(b * NN + n) << 4));
    const float4 a0 = a[0], a1 = a[1], a2 = a[2], a3 = a[3];
    const float av[16] = {a0.x,a0.y,a0.z,a0.w, a1.x,a1.y,a1.z,a1.w,
                          a2.x,a2.y,a2.z,a2.w, a3.x,a3.y,a3.z,a3.w};
    #pragma unroll
    for (int e = 0; e < 16; e++) {
        float acc = bsm[e];
        #pragma unroll
        for (int k = 0; k < 16; k++) acc = fmaf(av[k], Wsm[e][k], acc);
        thi[e][t] = __float2half_rn(acc);
    }
    __syncthreads();
    #pragma unroll
    for (int i = t; i < 2048; i += 256) {
        const int e = i >> 7, j = (i & 127) * 2;
        *(uint32_t*)(g_vh16 + ((size_t)bh * 16 + e) * NN + seg * 256 + j) =
            *(const uint32_t*)&thi[e][j];
    }
}

// ---------------- Q/K projection on tensor cores ----------------
__global__ void __launch_bounds__(256) projqk_mma_kernel(
    const float* __restrict__ Aq, const float* __restrict__ Ak,
    const float* __restrict__ bq, const float* __restrict__ bk, float alpha_q)
{
    const bool is_k = (blockIdx.y != 0);
    const float* A    = is_k ? Ak : Aq;
    const float* bias = is_k ? bk : bq;
    const __half* Wh  = g_Wh + (is_k ? 16384 : 0);
    const __half* Wl  = g_Wl + (is_k ? 16384 : 0);
    __half* outp      = is_k ? g_k16 : g_q16;
    const float alpha = is_k ? 1.0f : alpha_q;

    const int tid = threadIdx.x, lane = tid & 31, wid = tid >> 5;
    const int rg = wid >> 1, cg = wid & 1;
    const int lq = lane >> 2, lc = lane & 3;
    const int r0 = blockIdx.x * 64 + rg * 16;
    const int c0 = cg * 64;

    uint32_t ah[8][4], al[8][4];
    {
        const float* Ar0 = A + (size_t)(r0 + lq) * 128;
        const float* Ar1 = Ar0 + 8 * 128;
        #pragma unroll
        for (int ks = 0; ks < 8; ks++) {
            const int k0 = ks * 16 + lc * 2;
            float2 f0 = *(const float2*)(Ar0 + k0);
            float2 f1 = *(const float2*)(Ar1 + k0);
            float2 f2 = *(const float2*)(Ar0 + k0 + 8);
            float2 f3 = *(const float2*)(Ar1 + k0 + 8);
            ah[ks][0] = cvt_h2(f0.x, f0.y);
            ah[ks][1] = cvt_h2(f1.x, f1.y);
            ah[ks][2] = cvt_h2(f2.x, f2.y);
            ah[ks][3] = cvt_h2(f3.x, f3.y);
            float2 h0 = h2_to_f2(ah[ks][0]), h1 = h2_to_f2(ah[ks][1]);
            float2 h2 = h2_to_f2(ah[ks][2]), h3 = h2_to_f2(ah[ks][3]);
            al[ks][0] = cvt_h2(f0.x - h0.x, f0.y - h0.y);
            al[ks][1] = cvt_h2(f1.x - h1.x, f1.y - h1.y);
            al[ks][2] = cvt_h2(f2.x - h2.x, f2.y - h2.y);
            al[ks][3] = cvt_h2(f3.x - h3.x, f3.y - h3.y);
        }
    }

    float D[8][4];
    #pragma unroll
    for (int nb = 0; nb < 8; nb++)
        #pragma unroll
        for (int i = 0; i < 4; i++) D[nb][i] = 0.f;

    #pragma unroll
    for (int nb = 0; nb < 8; nb++) {
        const int c = c0 + nb * 8 + lq;
        const __half* whp = Wh + (size_t)c * 128;
        const __half* wlp = Wl + (size_t)c * 128;
        #pragma unroll
        for (int ks = 0; ks < 8; ks++) {
            const int k0 = ks * 16 + lc * 2;
            const uint32_t bh0 = *(const uint32_t*)(whp + k0);
            const uint32_t bh1 = *(const uint32_t*)(whp + k0 + 8);
            const uint32_t bl0 = *(const uint32_t*)(wlp + k0);
            const uint32_t bl1 = *(const uint32_t*)(wlp + k0 + 8);
            mma_f16(D[nb], ah[ks], bh0, bh1);
            mma_f16(D[nb], al[ks], bh0, bh1);
            mma_f16(D[nb], ah[ks], bl0, bl1);
        }
    }

    #pragma unroll
    for (int nb = 0; nb < 8; nb++) {
        const int ce = c0 + nb * 8 + lc * 2;
        const float2 bb = *(const float2*)(bias + ce);
        const int h = ce >> 4, d = ce & 15;
        #pragma unroll
        for (int rr = 0; rr < 2; rr++) {
            const int row = r0 + lq + rr * 8;
            const int b = row >> 11, n = row & 2047;
            __half* base = outp + ((size_t)((b * 8 + h) * 2048 + n)) * 32;
            const float x0 = (D[nb][2*rr + 0] + bb.x) * alpha;
            const float x1 = (D[nb][2*rr + 1] + bb.y) * alpha;
            const uint32_t hi2 = cvt_h2(x0, x1);
            const float2 hf = h2_to_f2(hi2);
            const uint32_t lo2 = cvt_h2(x0 - hf.x, x1 - hf.y);
            *(uint32_t*)(base + d)      = hi2;
            *(uint32_t*)(base + 16 + d) = lo2;
        }
    }
}

// ---------------- fp16 mma.sync flash attention + HMMA-fused out projection ----------------
// 1024 CTAs = 32 bh x 32 q-tiles of 64 rows; 4 warps; warp owns 16 q-rows; 4 CTAs/SM.
// l computed on the tensor pipe via an all-ones V column (n-block 2 of the V tile).
__global__ void __launch_bounds__(128, 4) attn_mma_kernel(float* __restrict__ out)
{
    __shared__ __align__(16) __half Ksm[128 * 40];   // [key][hi16|lo16|pad8]
    __shared__ __align__(16) __half Vh[24 * 136];    // [e][key]; rows 16..23: ones|zeros

    const int tid = threadIdx.x, lane = tid & 31, wid = tid >> 5;
    const int bh = blockIdx.x >> 5, qt = blockIdx.x & 31;
    const int qrow0 = qt * 64 + wid * 16;
    const int lq = lane >> 2;
    const int lc = lane & 3;

    uint32_t qh[4], ql[4];
    {
        const __half* p0 = g_q16 + ((size_t)(bh * NN + qrow0 + lq)) * 32 + lc * 2;
        qh[0] = *(const uint32_t*)(p0);
        qh[1] = *(const uint32_t*)(p0 + 256);
        qh[2] = *(const uint32_t*)(p0 + 8);
        qh[3] = *(const uint32_t*)(p0 + 264);
        ql[0] = *(const uint32_t*)(p0 + 16);
        ql[1] = *(const uint32_t*)(p0 + 272);
        ql[2] = *(const uint32_t*)(p0 + 24);
        ql[3] = *(const uint32_t*)(p0 + 280);
    }

    // ones-extension rows (constant across tiles): row 16 = 1.0, rows 17..23 = 0
    {
        const __half one = __float2half_rn(1.0f);
        const __half zer = __float2half_rn(0.0f);
        for (int i = tid; i < 8 * 136; i += 128)
            Vh[16 * 136 + i] = (i < 136) ? one : zer;
    }

    float mr[2] = {-1e30f, -1e30f};
    float o[2][4], o2[4];
    #pragma unroll
    for (int nb = 0; nb < 2; nb++)
        #pragma unroll
        for (int i = 0; i < 4; i++) o[nb][i] = 0.f;
    #pragma unroll
    for (int i = 0; i < 4; i++) o2[i] = 0.f;

    const uint4* kg = (const uint4*)(g_k16 + ((size_t)bh * NN) * 32);
    const __half* vhg = g_vh16 + (size_t)bh * 16 * NN;

    for (int t0 = 0; t0 < NN; t0 += 128) {
        __syncthreads();
        #pragma unroll
        for (int g = 0; g < 4; g++) {
            const int j = tid + 128 * g;
            const int key = j >> 2, seg = j & 3;
            *(uint4*)(Ksm + key * 40 + seg * 8) = kg[(size_t)t0 * 4 + j];
        }
        #pragma unroll
        for (int g = 0; g < 2; g++) {
            const int j = tid + 128 * g;
            const int e = j >> 4, seg = j & 15;
            *(uint4*)(Vh + e * 136 + seg * 8) = *(const uint4*)(vhg + (size_t)e * NN + t0 + seg * 8);
        }
        __syncthreads();

        // ---- QK: 3 compensated MMAs per n-block ----
        float S[16][4];
        #pragma unroll
        for (int n = 0; n < 16; n++)
            #pragma unroll
            for (int i = 0; i < 4; i++) S[n][i] = 0.f;

        #pragma unroll
        for (int n = 0; n < 16; n++) {
            const __half* kb = Ksm + (n * 8 + lq) * 40 + lc * 2;
            const uint32_t bh0 = *(const uint32_t*)kb;
            const uint32_t bh1 = *(const uint32_t*)(kb + 8);
            const uint32_t bl0 = *(const uint32_t*)(kb + 16);
            const uint32_t bl1 = *(const uint32_t*)(kb + 24);
            mma_f16(S[n], qh, bh0, bh1);
            mma_f16(S[n], ql, bh0, bh1);
            mma_f16(S[n], qh, bl0, bl1);
        }

        // ---- softmax (rows lq, lq+8) ----
        float cm0 = -1e30f, cm1 = -1e30f;
        #pragma unroll
        for (int n = 0; n < 16; n++) {
            cm0 = fmaxf(cm0, fmaxf(S[n][0], S[n][1]));
            cm1 = fmaxf(cm1, fmaxf(S[n][2], S[n][3]));
        }
        {
            const float mn0 = fmaxf(mr[0], qmax(cm0));
            const float c0 = ex2f_fast(mr[0] - mn0);
            mr[0] = mn0;
            const float mn1 = fmaxf(mr[1], qmax(cm1));
            const float c1 = ex2f_fast(mr[1] - mn1);
            mr[1] = mn1;
            #pragma unroll
            for (int nb = 0; nb < 2; nb++) {
                o[nb][0] *= c0; o[nb][1] *= c0;
                o[nb][2] *= c1; o[nb][3] *= c1;
            }
            o2[0] *= c0; o2[1] *= c0;
            o2[2] *= c1; o2[3] *= c1;
        }
        #pragma unroll
        for (int n = 0; n < 16; n++) {
            const float p0 = ex2f_fast(S[n][0] - mr[0]);
            const float p1 = ex2f_fast(S[n][1] - mr[0]);
            const float p2 = ex2f_fast(S[n][2] - mr[1]);
            const float p3 = ex2f_fast(S[n][3] - mr[1]);
            S[n][0] = __uint_as_float(cvt_h2(p0, p1));  // PV A-frag: keys (2lc,2lc+1), row lq
            S[n][1] = __uint_as_float(cvt_h2(p2, p3));  // row lq+8
        }

        // ---- PV (+ l via ones column, n-block 2) ----
        #pragma unroll
        for (int kb = 0; kb < 8; kb++) {
            const uint32_t ah4[4] = {
                __float_as_uint(S[2*kb][0]),   __float_as_uint(S[2*kb][1]),
                __float_as_uint(S[2*kb+1][0]), __float_as_uint(S[2*kb+1][1])
            };
            #pragma unroll
            for (int nb = 0; nb < 2; nb++) {
                const __half* vb = Vh + (nb * 8 + lq) * 136 + kb * 16 + lc * 2;
                const uint32_t b0 = *(const uint32_t*)vb;
                const uint32_t b1 = *(const uint32_t*)(vb + 8);
                mma_f16(o[nb], ah4, b0, b1);
            }
            const __half* vb2 = Vh + (16 + lq) * 136 + kb * 16 + lc * 2;
            const uint32_t c0 = *(const uint32_t*)vb2;
            const uint32_t c1 = *(const uint32_t*)(vb2 + 8);
            mma_f16(o2, ah4, c0, c1);
        }
    }

    // ---- l broadcast from lc=0 lanes (col 16 of ones block) ----
    const float l0 = __shfl_sync(0xFFFFFFFFu, o2[0], lane & ~3);
    const float l1 = __shfl_sync(0xFFFFFFFFu, o2[2], lane & ~3);
    const float inv0 = 1.0f / l0;
    const float inv1 = 1.0f / l1;

    // ---- fused out projection: ctx-frag @ Wo_h^T (hi/lo compensated) + REDG ----
    const int b = bh >> 3, hh = bh & 7;
    const int rA = qrow0 + lq;

    const uint32_t pa[4] = {
        cvt_h2(o[0][0] * inv0, o[0][1] * inv0),   // row lq,   e = 2lc, 2lc+1
        cvt_h2(o[0][2] * inv1, o[0][3] * inv1),   // row lq+8, e = 2lc, 2lc+1
        cvt_h2(o[1][0] * inv0, o[1][1] * inv0),   // row lq,   e = 8+2lc, 8+2lc+1
        cvt_h2(o[1][2] * inv1, o[1][3] * inv1)    // row lq+8, e = 8+2lc, 8+2lc+1
    };
    const __half* wbh = g_Woh + hh * 256;
    const __half* wbl = g_Wol + hh * 256;
    float d0[4] = {0.f, 0.f, 0.f, 0.f};
    float d1[4] = {0.f, 0.f, 0.f, 0.f};
    {
        const uint32_t b0h = *(const uint32_t*)(wbh + lq * 16 + lc * 2);
        const uint32_t b1h = *(const uint32_t*)(wbh + lq * 16 + lc * 2 + 8);
        const uint32_t b0l = *(const uint32_t*)(wbl + lq * 16 + lc * 2);
        const uint32_t b1l = *(const uint32_t*)(wbl + lq * 16 + lc * 2 + 8);
        mma_f16(d0, pa, b0h, b1h);
        mma_f16(d0, pa, b0l, b1l);
    }
    {
        const uint32_t b0h = *(const uint32_t*)(wbh + (8 + lq) * 16 + lc * 2);
        const uint32_t b1h = *(const uint32_t*)(wbh + (8 + lq) * 16 + lc * 2 + 8);
        const uint32_t b0l = *(const uint32_t*)(wbl + (8 + lq) * 16 + lc * 2);
        const uint32_t b1l = *(const uint32_t*)(wbl + (8 + lq) * 16 + lc * 2 + 8);
        mma_f16(d1, pa, b0h, b1h);
        mma_f16(d1, pa, b0l, b1l);
    }
    float* oA = out + (size_t)(b * NN + rA) * 16;
    float* oB = oA + 8 * 16;
    redg_f32(oA + 2*lc,     d0[0]); redg_f32(oA + 2*lc + 1,     d0[1]);
    redg_f32(oB + 2*lc,     d0[2]); redg_f32(oB + 2*lc + 1,     d0[3]);
    redg_f32(oA + 8 + 2*lc, d1[0]); redg_f32(oA + 8 + 2*lc + 1, d1[1]);
    redg_f32(oB + 8 + 2*lc, d1[2]); redg_f32(oB + 8 + 2*lc + 1, d1[3]);
}

// ---------------- launcher ----------------
extern "C" void kernel_launch(void* const* d_in, const int* in_sizes, int n_in,
                              void* d_out, int out_size)
{
    const float* query = (const float*)d_in[0];
    const float* key   = (const float*)d_in[1];
    const float* value = (const float*)d_in[2];
    const float* Wq    = (const float*)d_in[3];
    const float* bq    = (const float*)d_in[4];
    const float* Wk    = (const float*)d_in[5];
    const float* bk    = (const float*)d_in[6];
    const float* Wv    = (const float*)d_in[7];
    const float* bv    = (const float*)d_in[8];
    const float* Wo    = (const float*)d_in[9];
    const float* bo    = (const float*)d_in[10];
    float* out = (float*)d_out;

    const float alpha_q = 0.25f * 1.4426950408889634f;

    prep_kernel<<<456, 256>>>(value, Wv, bv, Wq, Wk, Wo, bo, out);
    projqk_mma_kernel<<<dim3(128, 2), 256>>>(query, key, bq, bk, alpha_q);
    attn_mma_kernel<<<BHN * 32, 128>>>(out);
}

// round 17
// speedup vs baseline: 1.2210x; 1.0228x over previous
#include <cuda_runtime.h>
#include <cuda_fp16.h>
#include <cstdint>

#define BB 4
#define HH 8
#define NN 2048
#define BHN (BB*HH)
#define MROWS (BB*NN)

// ---------------- scratch (static device, no allocs) ----------------
__device__ __half g_q16[BHN * NN * 32];   // [bh][n][qhi16|qlo16], 0.25*log2e folded
__device__ __half g_k16[BHN * NN * 32];   // [bh][n][khi16|klo16]
__device__ __half g_vh16[BHN * 16 * NN];  // [bh][e][n]  V^T (fp16-rn)
__device__ __half g_Wh[2 * 128 * 128];    // Wq/Wk hi: [q|k][c][k]
__device__ __half g_Wl[2 * 128 * 128];    // Wq/Wk lo residual
__device__ __half g_Woh[HH * 16 * 16];    // Wo hi: [h][c][e]
__device__ __half g_Wol[HH * 16 * 16];    // Wo lo residual

// ---------------- helpers ----------------
__device__ __forceinline__ float ex2f_fast(float x) {
    float y; asm("ex2.approx.ftz.f32 %0, %1;" : "=f"(y) : "f"(x)); return y;
}
__device__ __forceinline__ float qmax(float v) {
    v = fmaxf(v, __shfl_xor_sync(0xFFFFFFFFu, v, 1));
    v = fmaxf(v, __shfl_xor_sync(0xFFFFFFFFu, v, 2));
    return v;
}
__device__ __forceinline__ void mma_f16(float* d, const uint32_t* a,
                                        uint32_t b0, uint32_t b1) {
    asm volatile(
        "mma.sync.aligned.m16n8k16.row.col.f32.f16.f16.f32 "
        "{%0,%1,%2,%3}, {%4,%5,%6,%7}, {%8,%9}, {%0,%1,%2,%3};"
        : "+f"(d[0]), "+f"(d[1]), "+f"(d[2]), "+f"(d[3])
        : "r"(a[0]), "r"(a[1]), "r"(a[2]), "r"(a[3]), "r"(b0), "r"(b1));
}
// zero-accumulator variant: D = A*B + 0 (no S-init MOVs needed)
__device__ __forceinline__ void mma_f16_zc(float* d, const uint32_t* a,
                                           uint32_t b0, uint32_t b1) {
    asm volatile(
        "mma.sync.aligned.m16n8k16.row.col.f32.f16.f16.f32 "
        "{%0,%1,%2,%3}, {%4,%5,%6,%7}, {%8,%9}, {%10,%11,%12,%13};"
        : "=f"(d[0]), "=f"(d[1]), "=f"(d[2]), "=f"(d[3])
        : "r"(a[0]), "r"(a[1]), "r"(a[2]), "r"(a[3]), "r"(b0), "r"(b1),
          "f"(0.f), "f"(0.f), "f"(0.f), "f"(0.f));
}
// packs: low half <- lo, high half <- hi
__device__ __forceinline__ uint32_t cvt_h2(float lo, float hi) {
    uint32_t r;
    asm("cvt.rn.f16x2.f32 %0, %1, %2;" : "=r"(r) : "f"(hi), "f"(lo));
    return r;
}
__device__ __forceinline__ float2 h2_to_f2(uint32_t u) {
    return __half22float2(*reinterpret_cast<__half2*>(&u));
}
__device__ __forceinline__ void redg_f32(float* p, float v) {
    asm volatile("red.global.add.f32 [%0], %1;" :: "l"(p), "f"(v) : "memory");
}
__device__ __forceinline__ uint32_t smem_u32(const void* p) {
    uint32_t a;
    asm("{ .reg .u64 t; cvta.to.shared.u64 t, %1; cvt.u32.u64 %0, t; }" : "=r"(a) : "l"(p));
    return a;
}
__device__ __forceinline__ void cp_async16(uint32_t dst, const void* src) {
    asm volatile("cp.async.ca.shared.global [%0], [%1], 16;" :: "r"(dst), "l"(src));
}
#define CP_COMMIT()  asm volatile("cp.async.commit_group;" ::: "memory")
#define CP_WAIT1()   asm volatile("cp.async.wait_group 1;" ::: "memory")
#define CP_WAIT0()   asm volatile("cp.async.wait_group 0;" ::: "memory")

// ---------------- kernel 1: V proj+transpose, W splits, out<-bias ----------------
__global__ void __launch_bounds__(256) prep_kernel(
    const float* __restrict__ value, const float* __restrict__ Wv,
    const float* __restrict__ bv,
    const float* __restrict__ Wq, const float* __restrict__ Wk,
    const float* __restrict__ Wo, const float* __restrict__ bo,
    float* __restrict__ out)
{
    const int t = threadIdx.x;
    if (blockIdx.x >= 448) {
        const int idx = (blockIdx.x - 448) * 256 + t;   // 0..2047
        const int c = idx >> 7, rest = idx & 127;
        const int hh = rest >> 4, e = rest & 15;
        const float x = Wo[idx];
        const __half hi = __float2half_rn(x);
        g_Woh[hh * 256 + c * 16 + e] = hi;
        g_Wol[hh * 256 + c * 16 + e] = __float2half_rn(x - __half2float(hi));
        return;
    }
    if (blockIdx.x >= 384) {
        const int i = ((blockIdx.x - 384) * 256 + t) * 8;
        const int c = i & 15;
        const float4 b0 = *(const float4*)(bo + c);
        const float4 b1 = *(const float4*)(bo + c + 4);
        *(float4*)(out + i)     = b0;
        *(float4*)(out + i + 4) = b1;
        return;
    }
    if (blockIdx.x >= 256) {
        const int idx = (blockIdx.x - 256) * 256 + t;
        const int m = idx >> 14, rest = idx & 16383;
        const float x = (m ? Wk : Wq)[rest];
        const __half hi = __float2half_rn(x);
        g_Wh[idx] = hi;
        g_Wl[idx] = __float2half_rn(x - __half2float(hi));
        return;
    }
    __shared__ float Wsm[16][17];
    __shared__ float bsm[16];
    __shared__ __half thi[16][256];
    const int bh = blockIdx.x >> 3, seg = blockIdx.x & 7;
    const int b = bh >> 3, h = bh & 7;
    if (t < 16) bsm[t] = bv[h * 16 + t];
    if (t < 256) Wsm[t >> 4][t & 15] = Wv[(h * 16 + (t >> 4)) * 16 + (t & 15)];
    __syncthreads();
    const int n = seg * 256 + t;
    const float4* a = (const float4*)(value + ((size_t)(b * NN + n) << 4));
    const float4 a0 = a[0], a1 = a[1], a2 = a[2], a3 = a[3];
    const float av[16] = {a0.x,a0.y,a0.z,a0.w, a1.x,a1.y,a1.z,a1.w,
                          a2.x,a2.y,a2.z,a2.w, a3.x,a3.y,a3.z,a3.w};
    #pragma unroll
    for (int e = 0; e < 16; e++) {
        float acc = bsm[e];
        #pragma unroll
        for (int k = 0; k < 16; k++) acc = fmaf(av[k], Wsm[e][k], acc);
        thi[e][t] = __float2half_rn(acc);
    }
    __syncthreads();
    #pragma unroll
    for (int i = t; i < 2048; i += 256) {
        const int e = i >> 7, j = (i & 127) * 2;
        *(uint32_t*)(g_vh16 + ((size_t)bh * 16 + e) * NN + seg * 256 + j) =
            *(const uint32_t*)&thi[e][j];
    }
}

// ---------------- Q/K projection on tensor cores ----------------
__global__ void __launch_bounds__(256) projqk_mma_kernel(
    const float* __restrict__ Aq, const float* __restrict__ Ak,
    const float* __restrict__ bq, const float* __restrict__ bk, float alpha_q)
{
    const bool is_k = (blockIdx.y != 0);
    const float* A    = is_k ? Ak : Aq;
    const float* bias = is_k ? bk : bq;
    const __half* Wh  = g_Wh + (is_k ? 16384 : 0);
    const __half* Wl  = g_Wl + (is_k ? 16384 : 0);
    __half* outp      = is_k ? g_k16 : g_q16;
    const float alpha = is_k ? 1.0f : alpha_q;

    const int tid = threadIdx.x, lane = tid & 31, wid = tid >> 5;
    const int rg = wid >> 1, cg = wid & 1;
    const int lq = lane >> 2, lc = lane & 3;
    const int r0 = blockIdx.x * 64 + rg * 16;
    const int c0 = cg * 64;

    uint32_t ah[8][4], al[8][4];
    {
        const float* Ar0 = A + (size_t)(r0 + lq) * 128;
        const float* Ar1 = Ar0 + 8 * 128;
        #pragma unroll
        for (int ks = 0; ks < 8; ks++) {
            const int k0 = ks * 16 + lc * 2;
            float2 f0 = *(const float2*)(Ar0 + k0);
            float2 f1 = *(const float2*)(Ar1 + k0);
            float2 f2 = *(const float2*)(Ar0 + k0 + 8);
            float2 f3 = *(const float2*)(Ar1 + k0 + 8);
            ah[ks][0] = cvt_h2(f0.x, f0.y);
            ah[ks][1] = cvt_h2(f1.x, f1.y);
            ah[ks][2] = cvt_h2(f2.x, f2.y);
            ah[ks][3] = cvt_h2(f3.x, f3.y);
            float2 h0 = h2_to_f2(ah[ks][0]), h1 = h2_to_f2(ah[ks][1]);
            float2 h2 = h2_to_f2(ah[ks][2]), h3 = h2_to_f2(ah[ks][3]);
            al[ks][0] = cvt_h2(f0.x - h0.x, f0.y - h0.y);
            al[ks][1] = cvt_h2(f1.x - h1.x, f1.y - h1.y);
            al[ks][2] = cvt_h2(f2.x - h2.x, f2.y - h2.y);
            al[ks][3] = cvt_h2(f3.x - h3.x, f3.y - h3.y);
        }
    }

    float D[8][4];
    #pragma unroll
    for (int nb = 0; nb < 8; nb++)
        #pragma unroll
        for (int i = 0; i < 4; i++) D[nb][i] = 0.f;

    #pragma unroll
    for (int nb = 0; nb < 8; nb++) {
        const int c = c0 + nb * 8 + lq;
        const __half* whp = Wh + (size_t)c * 128;
        const __half* wlp = Wl + (size_t)c * 128;
        #pragma unroll
        for (int ks = 0; ks < 8; ks++) {
            const int k0 = ks * 16 + lc * 2;
            const uint32_t bh0 = *(const uint32_t*)(whp + k0);
            const uint32_t bh1 = *(const uint32_t*)(whp + k0 + 8);
            const uint32_t bl0 = *(const uint32_t*)(wlp + k0);
            const uint32_t bl1 = *(const uint32_t*)(wlp + k0 + 8);
            mma_f16(D[nb], ah[ks], bh0, bh1);
            mma_f16(D[nb], al[ks], bh0, bh1);
            mma_f16(D[nb], ah[ks], bl0, bl1);
        }
    }

    #pragma unroll
    for (int nb = 0; nb < 8; nb++) {
        const int ce = c0 + nb * 8 + lc * 2;
        const float2 bb = *(const float2*)(bias + ce);
        const int h = ce >> 4, d = ce & 15;
        #pragma unroll
        for (int rr = 0; rr < 2; rr++) {
            const int row = r0 + lq + rr * 8;
            const int b = row >> 11, n = row & 2047;
            __half* base = outp + ((size_t)((b * 8 + h) * 2048 + n)) * 32;
            const float x0 = (D[nb][2*rr + 0] + bb.x) * alpha;
            const float x1 = (D[nb][2*rr + 1] + bb.y) * alpha;
            const uint32_t hi2 = cvt_h2(x0, x1);
            const float2 hf = h2_to_f2(hi2);
            const uint32_t lo2 = cvt_h2(x0 - hf.x, x1 - hf.y);
            *(uint32_t*)(base + d)      = hi2;
            *(uint32_t*)(base + 16 + d) = lo2;
        }
    }
}

// ---------------- fp16 mma.sync flash attention + HMMA-fused out projection ----------------
// 1024 CTAs = 32 bh x 32 q-tiles of 64 rows; 4 warps; warp owns 16 q-rows; 4 CTAs/SM.
// cp.async double-buffered staging (V staged by 2 chunks/thread — full 16 rows).
__global__ void __launch_bounds__(128, 4) attn_mma_kernel(float* __restrict__ out)
{
    __shared__ __align__(16) __half Ksm[2][128 * 40];   // [buf][key][hi16|lo16|pad8]
    __shared__ __align__(16) __half Vst[2][16 * 136];   // [buf][e][key]
    __shared__ __align__(16) __half Vones[8 * 136];     // row0 = ones, rows 1..7 zeros

    const int tid = threadIdx.x, lane = tid & 31, wid = tid >> 5;
    const int bh = blockIdx.x >> 5, qt = blockIdx.x & 31;
    const int qrow0 = qt * 64 + wid * 16;
    const int lq = lane >> 2;
    const int lc = lane & 3;

    uint32_t qh[4], ql[4];
    {
        const __half* p0 = g_q16 + ((size_t)(bh * NN + qrow0 + lq)) * 32 + lc * 2;
        qh[0] = *(const uint32_t*)(p0);
        qh[1] = *(const uint32_t*)(p0 + 256);
        qh[2] = *(const uint32_t*)(p0 + 8);
        qh[3] = *(const uint32_t*)(p0 + 264);
        ql[0] = *(const uint32_t*)(p0 + 16);
        ql[1] = *(const uint32_t*)(p0 + 272);
        ql[2] = *(const uint32_t*)(p0 + 24);
        ql[3] = *(const uint32_t*)(p0 + 280);
    }
    {
        const __half one = __float2half_rn(1.0f);
        const __half zer = __float2half_rn(0.0f);
        for (int i = tid; i < 8 * 136; i += 128)
            Vones[i] = (i < 136) ? one : zer;
    }

    float mr[2] = {-1e30f, -1e30f};
    float o[2][4], o2[4];
    #pragma unroll
    for (int nb = 0; nb < 2; nb++)
        #pragma unroll
        for (int i = 0; i < 4; i++) o[nb][i] = 0.f;
    #pragma unroll
    for (int i = 0; i < 4; i++) o2[i] = 0.f;

    const char* kgc = (const char*)(g_k16 + ((size_t)bh * NN) * 32);
    const __half* vhg = g_vh16 + (size_t)bh * 16 * NN;

    // per-thread staging coordinates: 4 K chunks + 2 V chunks per thread
    const uint32_t ksb = smem_u32(&Ksm[0][0]);
    const uint32_t vsb = smem_u32(&Vst[0][0]);
    const int ve0 = tid >> 4,        vseg0 = tid & 15;          // rows 0..7
    const int ve1 = (tid + 128) >> 4, vseg1 = tid & 15;          // rows 8..15
    const uint32_t vdst0 = (uint32_t)(ve0 * 272 + vseg0 * 16);
    const uint32_t vdst1 = (uint32_t)(ve1 * 272 + vseg1 * 16);
    const char* vsrc0 = (const char*)(vhg + (size_t)ve0 * NN) + vseg0 * 16;
    const char* vsrc1 = (const char*)(vhg + (size_t)ve1 * NN) + vseg1 * 16;

    #define STAGE(T0, BUF) do { \
        const uint32_t kb_ = ksb + (BUF) * 10240; \
        _Pragma("unroll") \
        for (int g_ = 0; g_ < 4; g_++) { \
            const int j_ = tid + 128 * g_; \
            const int key_ = j_ >> 2, seg_ = j_ & 3; \
            cp_async16(kb_ + (uint32_t)(key_ * 80 + seg_ * 16), \
                       kgc + (size_t)((T0) + key_) * 64 + seg_ * 16); \
        } \
        cp_async16(vsb + (BUF) * 4352 + vdst0, vsrc0 + (size_t)(T0) * 2); \
        cp_async16(vsb + (BUF) * 4352 + vdst1, vsrc1 + (size_t)(T0) * 2); \
        CP_COMMIT(); \
    } while (0)

    STAGE(0, 0);

    for (int t = 0; t < 16; t++) {
        const int cur = t & 1;
        if (t < 15) { STAGE((t + 1) * 128, 1 - cur); CP_WAIT1(); }
        else        { CP_WAIT0(); }
        __syncthreads();

        const __half* Kb = Ksm[cur];
        const __half* Vb = Vst[cur];

        // ---- QK: zero-C first MMA + 2 compensated ----
        float S[16][4];
        #pragma unroll
        for (int n = 0; n < 16; n++) {
            const __half* kb = Kb + (n * 8 + lq) * 40 + lc * 2;
            const uint32_t bh0 = *(const uint32_t*)kb;
            const uint32_t bh1 = *(const uint32_t*)(kb + 8);
            const uint32_t bl0 = *(const uint32_t*)(kb + 16);
            const uint32_t bl1 = *(const uint32_t*)(kb + 24);
            mma_f16_zc(S[n], qh, bh0, bh1);
            mma_f16(S[n], ql, bh0, bh1);
            mma_f16(S[n], qh, bl0, bl1);
        }

        // ---- softmax (rows lq, lq+8) ----
        float cm0 = -1e30f, cm1 = -1e30f;
        #pragma unroll
        for (int n = 0; n < 16; n++) {
            cm0 = fmaxf(cm0, fmaxf(S[n][0], S[n][1]));
            cm1 = fmaxf(cm1, fmaxf(S[n][2], S[n][3]));
        }
        {
            const float mn0 = fmaxf(mr[0], qmax(cm0));
            const float c0 = ex2f_fast(mr[0] - mn0);
            mr[0] = mn0;
            const float mn1 = fmaxf(mr[1], qmax(cm1));
            const float c1 = ex2f_fast(mr[1] - mn1);
            mr[1] = mn1;
            #pragma unroll
            for (int nb = 0; nb < 2; nb++) {
                o[nb][0] *= c0; o[nb][1] *= c0;
                o[nb][2] *= c1; o[nb][3] *= c1;
            }
            o2[0] *= c0; o2[1] *= c0;
            o2[2] *= c1; o2[3] *= c1;
        }
        #pragma unroll
        for (int n = 0; n < 16; n++) {
            const float p0 = ex2f_fast(S[n][0] - mr[0]);
            const float p1 = ex2f_fast(S[n][1] - mr[0]);
            const float p2 = ex2f_fast(S[n][2] - mr[1]);
            const float p3 = ex2f_fast(S[n][3] - mr[1]);
            S[n][0] = __uint_as_float(cvt_h2(p0, p1));  // keys (2lc,2lc+1), row lq
            S[n][1] = __uint_as_float(cvt_h2(p2, p3));  // row lq+8
        }

        // ---- PV (+ l via ones row) ----
        #pragma unroll
        for (int kb = 0; kb < 8; kb++) {
            const uint32_t ah4[4] = {
                __float_as_uint(S[2*kb][0]),   __float_as_uint(S[2*kb][1]),
                __float_as_uint(S[2*kb+1][0]), __float_as_uint(S[2*kb+1][1])
            };
            #pragma unroll
            for (int nb = 0; nb < 2; nb++) {
                const __half* vb = Vb + (nb * 8 + lq) * 136 + kb * 16 + lc * 2;
                const uint32_t b0 = *(const uint32_t*)vb;
                const uint32_t b1 = *(const uint32_t*)(vb + 8);
                mma_f16(o[nb], ah4, b0, b1);
            }
            const __half* vb2 = Vones + lq * 136 + kb * 16 + lc * 2;
            const uint32_t c0 = *(const uint32_t*)vb2;
            const uint32_t c1 = *(const uint32_t*)(vb2 + 8);
            mma_f16(o2, ah4, c0, c1);
        }
        __syncthreads();
    }
    #undef STAGE

    // ---- l broadcast from lc=0 lanes ----
    const float l0 = __shfl_sync(0xFFFFFFFFu, o2[0], lane & ~3);
    const float l1 = __shfl_sync(0xFFFFFFFFu, o2[2], lane & ~3);
    const float inv0 = 1.0f / l0;
    const float inv1 = 1.0f / l1;

    // ---- fused out projection: ctx-frag @ Wo_h^T (hi/lo compensated) + REDG ----
    const int b = bh >> 3, hh = bh & 7;
    const int rA = qrow0 + lq;
    const uint32_t pa[4] = {
        cvt_h2(o[0][0] * inv0, o[0][1] * inv0),
        cvt_h2(o[0][2] * inv1, o[0][3] * inv1),
        cvt_h2(o[1][0] * inv0, o[1][1] * inv0),
        cvt_h2(o[1][2] * inv1, o[1][3] * inv1)
    };
    const __half* wbh = g_Woh + hh * 256;
    const __half* wbl = g_Wol + hh * 256;
    float d0[4], d1[4];
    {
        const uint32_t b0h = *(const uint32_t*)(wbh + lq * 16 + lc * 2);
        const uint32_t b1h = *(const uint32_t*)(wbh + lq * 16 + lc * 2 + 8);
        const uint32_t b0l = *(const uint32_t*)(wbl + lq * 16 + lc * 2);
        const uint32_t b1l = *(const uint32_t*)(wbl + lq * 16 + lc * 2 + 8);
        mma_f16_zc(d0, pa, b0h, b1h);
        mma_f16(d0, pa, b0l, b1l);
    }
    {
        const uint32_t b0h = *(const uint32_t*)(wbh + (8 + lq) * 16 + lc * 2);
        const uint32_t b1h = *(const uint32_t*)(wbh + (8 + lq) * 16 + lc * 2 + 8);
        const uint32_t b0l = *(const uint32_t*)(wbl + (8 + lq) * 16 + lc * 2);
        const uint32_t b1l = *(const uint32_t*)(wbl + (8 + lq) * 16 + lc * 2 + 8);
        mma_f16_zc(d1, pa, b0h, b1h);
        mma_f16(d1, pa, b0l, b1l);
    }
    float* oA = out + (size_t)(b * NN + rA) * 16;
    float* oB = oA + 8 * 16;
    redg_f32(oA + 2*lc,     d0[0]); redg_f32(oA + 2*lc + 1,     d0[1]);
    redg_f32(oB + 2*lc,     d0[2]); redg_f32(oB + 2*lc + 1,     d0[3]);
    redg_f32(oA + 8 + 2*lc, d1[0]); redg_f32(oA + 8 + 2*lc + 1, d1[1]);
    redg_f32(oB + 8 + 2*lc, d1[2]); redg_f32(oB + 8 + 2*lc + 1, d1[3]);
}

// ---------------- launcher ----------------
extern "C" void kernel_launch(void* const* d_in, const int* in_sizes, int n_in,
                              void* d_out, int out_size)
{
    const float* query = (const float*)d_in[0];
    const float* key   = (const float*)d_in[1];
    const float* value = (const float*)d_in[2];
    const float* Wq    = (const float*)d_in[3];
    const float* bq    = (const float*)d_in[4];
    const float* Wk    = (const float*)d_in[5];
    const float* bk    = (const float*)d_in[6];
    const float* Wv    = (const float*)d_in[7];
    const float* bv    = (const float*)d_in[8];
    const float* Wo    = (const float*)d_in[9];
    const float* bo    = (const float*)d_in[10];
    float* out = (float*)d_out;

    const float alpha_q = 0.25f * 1.4426950408889634f;

    prep_kernel<<<456, 256>>>(value, Wv, bv, Wq, Wk, Wo, bo, out);
    projqk_mma_kernel<<<dim3(128, 2), 256>>>(query, key, bq, bk, alpha_q);
    attn_mma_kernel<<<BHN * 32, 128>>>(out);
}